// round 10
// baseline (speedup 1.0000x reference)
#include <cuda_runtime.h>
#include <cuda_bf16.h>
#include <cstdint>

// Problem constants
#define LSEQ   2048
#define NB     2
#define DMODEL 2048
#define NQKV   3072
#define KVW    512
#define HD     64
#define MROWS  (NB * LSEQ)   // 4096

#define QSCALE 0.18033688011f   // 0.125 * log2(e): folded into Q at projection epilogue

// ---------------- scratch (device globals; no allocation allowed) ----------------
__device__ __nv_bfloat16 g_xh [MROWS * DMODEL], g_xl [MROWS * DMODEL];
__device__ __nv_bfloat16 g_aoh[MROWS * DMODEL], g_aol[MROWS * DMODEL];
__device__ __nv_bfloat16 g_wqh[NQKV * DMODEL],  g_wql[NQKV * DMODEL];    // W_qkv^T (N,K)
__device__ __nv_bfloat16 g_woh[DMODEL * DMODEL], g_wol[DMODEL * DMODEL]; // W_out^T (N,K)
// Q/K/V bf16 hi/lo. Plain-reshape semantics: head gh's Q is the CONTIGUOUS
// (LSEQ, 64) slab at gh*LSEQ*HD (row stride 64); K/V head h at h*LSEQ*HD.
__device__ __nv_bfloat16 g_Qh[MROWS * DMODEL], g_Ql[MROWS * DMODEL];
__device__ __nv_bfloat16 g_Kh[MROWS * KVW],    g_Kl[MROWS * KVW];
__device__ __nv_bfloat16 g_Vh[MROWS * KVW],    g_Vl[MROWS * KVW];

// ---------------- PTX helpers (portable ISA: sm_80+) ----------------
__device__ __forceinline__ uint32_t s2u(const void* p) {
    uint32_t a;
    asm("{ .reg .u64 t; cvta.to.shared.u64 t, %1; cvt.u32.u64 %0, t; }" : "=r"(a) : "l"(p));
    return a;
}

__device__ __forceinline__ void ldm4(uint32_t* r, uint32_t addr) {
    asm volatile("ldmatrix.sync.aligned.m8n8.x4.shared.b16 {%0,%1,%2,%3}, [%4];"
                 : "=r"(r[0]), "=r"(r[1]), "=r"(r[2]), "=r"(r[3]) : "r"(addr));
}
__device__ __forceinline__ void ldm4t(uint32_t* r, uint32_t addr) {
    asm volatile("ldmatrix.sync.aligned.m8n8.x4.trans.shared.b16 {%0,%1,%2,%3}, [%4];"
                 : "=r"(r[0]), "=r"(r[1]), "=r"(r[2]), "=r"(r[3]) : "r"(addr));
}

__device__ __forceinline__ void mma16816(float* d, const uint32_t* a, const uint32_t* b) {
    asm volatile("mma.sync.aligned.m16n8k16.row.col.f32.bf16.bf16.f32 "
                 "{%0,%1,%2,%3}, {%4,%5,%6,%7}, {%8,%9}, {%0,%1,%2,%3};"
                 : "+f"(d[0]), "+f"(d[1]), "+f"(d[2]), "+f"(d[3])
                 : "r"(a[0]), "r"(a[1]), "r"(a[2]), "r"(a[3]), "r"(b[0]), "r"(b[1]));
}

#define CPASYNC(dst, src) \
    asm volatile("cp.async.cg.shared.global [%0], [%1], 16;" :: "r"(dst), "l"(src))
#define CPCOMMIT() asm volatile("cp.async.commit_group;")
#define CPWAIT(n)  asm volatile("cp.async.wait_group %0;" :: "n"(n))

__device__ __forceinline__ uint32_t packbf(float lo_, float hi_) {
    __nv_bfloat162 t;
    t.x = __float2bfloat16(lo_);
    t.y = __float2bfloat16(hi_);
    return *(uint32_t*)&t;
}

// fast exp2 for t <= 0 (degree-6, rel err ~1.2e-5), FMA-pipe only
__device__ __forceinline__ float exp2p(float t) {
    t = fmaxf(t, -126.0f);
    float fl = floorf(t);
    float f  = t - fl;
    float p  = 1.5403530e-4f;
    p = p * f + 1.3333558e-3f;
    p = p * f + 9.6181291e-3f;
    p = p * f + 5.5504109e-2f;
    p = p * f + 2.4022651e-1f;
    p = p * f + 6.9314718e-1f;
    p = p * f + 1.0f;
    int i = (int)fl;
    return p * __int_as_float((uint32_t)(i + 127) << 23);
}

// ---------------- conversion kernels ----------------
__global__ void split_convert(const float* __restrict__ src, int n4)
{
    int i = blockIdx.x * blockDim.x + threadIdx.x;
    if (i >= n4) return;
    float4 v = ((const float4*)src)[i];
    float f[4] = {v.x, v.y, v.z, v.w};
    __nv_bfloat16 h[4], l[4];
    #pragma unroll
    for (int j = 0; j < 4; j++) {
        h[j] = __float2bfloat16(f[j]);
        l[j] = __float2bfloat16(f[j] - __bfloat162float(h[j]));
    }
    *(uint2*)(g_xh + 4 * (size_t)i) = *(uint2*)h;
    *(uint2*)(g_xl + 4 * (size_t)i) = *(uint2*)l;
}

__global__ void transpose_convert(const float* __restrict__ in, int N, int sel)
{
    __shared__ float t[32][33];
    __nv_bfloat16* hi = sel ? g_woh : g_wqh;
    __nv_bfloat16* lo = sel ? g_wol : g_wql;
    const int n0 = blockIdx.x * 32, k0 = blockIdx.y * 32;
    const int tx = threadIdx.x, ty = threadIdx.y;
    #pragma unroll
    for (int j = 0; j < 32; j += 8)
        t[ty + j][tx] = in[(size_t)(k0 + ty + j) * N + n0 + tx];
    __syncthreads();
    #pragma unroll
    for (int j = 0; j < 32; j += 8) {
        float v = t[tx][ty + j];
        int n = n0 + ty + j, k = k0 + tx;
        __nv_bfloat16 h = __float2bfloat16(v);
        hi[(size_t)n * DMODEL + k] = h;
        lo[(size_t)n * DMODEL + k] = __float2bfloat16(v - __bfloat162float(h));
    }
}

// ---------------- mma.sync bf16x3 GEMM: 128x128 block, K=2048, 4-stage ----------------
#define BKC 32
#define TROW 80                       // smem bytes per 32-bf16 row (ldmatrix conflict-free)
#define TILE_BYTES (128 * TROW)
#define STAGE_BYTES (4 * TILE_BYTES)
#define GSTAGES 4
#define GSMEM (GSTAGES * STAGE_BYTES) // 163840
#define NCHUNK (DMODEL / BKC)         // 64

template<int MODE>
__global__ void __launch_bounds__(256)
gemm_mma(float* __restrict__ Cout)
{
    extern __shared__ char smem[];
    const uint32_t sb = s2u(smem);
    const int tid = threadIdx.x, wid = tid >> 5, lane = tid & 31;
    const int wm = wid >> 1, wn = wid & 1;

    const __nv_bfloat16 *Ah, *Al, *Bh, *Bl;
    if (MODE == 1) { Ah = g_xh;  Al = g_xl;  Bh = g_wqh; Bl = g_wql; }
    else           { Ah = g_aoh; Al = g_aol; Bh = g_woh; Bl = g_wol; }

    const int bm = blockIdx.y * 128;
    const int bn = blockIdx.x * 128;

    float acc[2][8][4];
    #pragma unroll
    for (int i = 0; i < 2; i++)
        #pragma unroll
        for (int j = 0; j < 8; j++)
            #pragma unroll
            for (int q = 0; q < 4; q++) acc[i][j][q] = 0.f;

    const int lrow0 = tid >> 2;
    const int lck   = tid & 3;

    auto issue_load = [&](int stage, int c) {
        const uint32_t so = sb + (uint32_t)stage * STAGE_BYTES;
        const int kc = c * BKC;
        const __nv_bfloat16* srcs[4] = {Ah, Al, Bh, Bl};
        #pragma unroll
        for (int t = 0; t < 4; t++) {
            const int rb = (t < 2) ? bm : bn;
            const __nv_bfloat16* s = srcs[t];
            #pragma unroll
            for (int half = 0; half < 2; half++) {
                int row = lrow0 + half * 64;
                uint32_t dst = so + (uint32_t)t * TILE_BYTES + row * TROW + lck * 16;
                const void* src = s + (size_t)(rb + row) * DMODEL + kc + lck * 8;
                CPASYNC(dst, src);
            }
        }
        CPCOMMIT();
    };

    issue_load(0, 0);
    issue_load(1, 1);
    issue_load(2, 2);

    const uint32_t aq = (lane & 7) + ((lane >> 3) & 1) * 8;
    const uint32_t ak = (lane >> 4) * 8;
    const uint32_t bq = (lane & 7) + (lane >> 4) * 8;
    const uint32_t bk = ((lane >> 3) & 1) * 8;

    for (int c = 0; c < NCHUNK; c++) {
        CPWAIT(2);
        __syncthreads();   // single barrier per chunk

        const uint32_t so = sb + (uint32_t)(c & 3) * STAGE_BYTES;

        #pragma unroll
        for (int ks = 0; ks < 2; ks++) {
            uint32_t afh[2][4], afl[2][4];
            #pragma unroll
            for (int i = 0; i < 2; i++) {
                uint32_t addr = so + (wm * 32 + i * 16 + aq) * TROW + (ks * 16 + ak) * 2;
                ldm4(afh[i], addr);
                ldm4(afl[i], addr + TILE_BYTES);
            }
            uint32_t bfh[8][2], bfl[8][2];
            #pragma unroll
            for (int jj = 0; jj < 4; jj++) {
                uint32_t addr = so + 2 * TILE_BYTES
                              + (wn * 64 + jj * 16 + bq) * TROW + (ks * 16 + bk) * 2;
                uint32_t r[4];
                ldm4(r, addr);
                bfh[jj*2][0] = r[0]; bfh[jj*2][1] = r[1];
                bfh[jj*2+1][0] = r[2]; bfh[jj*2+1][1] = r[3];
                ldm4(r, addr + TILE_BYTES);
                bfl[jj*2][0] = r[0]; bfl[jj*2][1] = r[1];
                bfl[jj*2+1][0] = r[2]; bfl[jj*2+1][1] = r[3];
            }
            #pragma unroll
            for (int i = 0; i < 2; i++)
                #pragma unroll
                for (int j = 0; j < 8; j++) {
                    mma16816(acc[i][j], afh[i], bfh[j]);
                    mma16816(acc[i][j], afh[i], bfl[j]);
                    mma16816(acc[i][j], afl[i], bfh[j]);
                }
        }

        // prefetch chunk c+3 into the buffer consumed at iter c-1 (barrier-safe)
        if (c + 3 < NCHUNK) issue_load((c + 3) & 3, c + 3);
        else                CPCOMMIT();   // empty group keeps wait_group math exact
    }

    // ---- epilogue ----
    const int g = lane >> 2, tg = lane & 3;
    if (MODE == 0) {
        #pragma unroll
        for (int i = 0; i < 2; i++) {
            const int r0 = bm + wm * 32 + i * 16 + g;
            #pragma unroll
            for (int j = 0; j < 8; j++) {
                const int cc = bn + wn * 64 + j * 8 + tg * 2;
                *(float2*)(Cout + (size_t)r0 * DMODEL + cc)       = make_float2(acc[i][j][0], acc[i][j][1]);
                *(float2*)(Cout + (size_t)(r0 + 8) * DMODEL + cc) = make_float2(acc[i][j][2], acc[i][j][3]);
            }
        }
    } else {
        __nv_bfloat16 *dh, *dl; int ldd, c0; float scale;
        if (bn < DMODEL)            { dh = g_Qh; dl = g_Ql; ldd = DMODEL; c0 = bn;                scale = QSCALE; }
        else if (bn < DMODEL + KVW) { dh = g_Kh; dl = g_Kl; ldd = KVW;   c0 = bn - DMODEL;        scale = 1.f; }
        else                        { dh = g_Vh; dl = g_Vl; ldd = KVW;   c0 = bn - DMODEL - KVW;  scale = 1.f; }
        #pragma unroll
        for (int i = 0; i < 2; i++) {
            const int r0 = bm + wm * 32 + i * 16 + g;
            #pragma unroll
            for (int j = 0; j < 8; j++) {
                const int cc = c0 + wn * 64 + j * 8 + tg * 2;
                #pragma unroll
                for (int rr = 0; rr < 2; rr++) {
                    float v0 = acc[i][j][rr*2 + 0] * scale;
                    float v1 = acc[i][j][rr*2 + 1] * scale;
                    __nv_bfloat16 h0 = __float2bfloat16(v0);
                    __nv_bfloat16 h1 = __float2bfloat16(v1);
                    float l0 = v0 - __bfloat162float(h0);
                    float l1 = v1 - __bfloat162float(h1);
                    size_t off = (size_t)(r0 + rr * 8) * ldd + cc;
                    __nv_bfloat162 hp; hp.x = h0; hp.y = h1;
                    *(uint32_t*)(dh + off) = *(uint32_t*)&hp;
                    *(uint32_t*)(dl + off) = packbf(l0, l1);
                }
            }
        }
    }
}

// ---------------- flash attention, mma.sync bf16x3, Br=128 Bc=64, 3-stage ----------------
#define FA_T 256
#define FTROW 144                       // 64 bf16 = 128B data + 16B pad
#define QSM_B (128 * FTROW)             // 18432 per Q version
#define FKV_TILE (64 * FTROW)           // 9216
#define FSTAGE (4 * FKV_TILE)           // Kh,Kl,Vh,Vl = 36864
#define FA_STAGES 3
#define FA_SMEM (2 * QSM_B + FA_STAGES * FSTAGE)  // 147456

__global__ void __launch_bounds__(FA_T)
fa_mma()
{
    extern __shared__ char smem[];
    const uint32_t sb = s2u(smem);
    const int tid = threadIdx.x, wm = tid >> 5, lane = tid & 31;
    const int g = lane >> 2, tg = lane & 3;

    const int qt = blockIdx.x;
    const int gh = blockIdx.y;
    const int b  = blockIdx.z;
    const int h  = gh & 7;
    const int q0 = qt * 128;
    const int jmax = 2 * qt + 1;

    const size_t qbase = (size_t)b * LSEQ * DMODEL + (size_t)gh * LSEQ * HD;
    const size_t kbase = (size_t)b * LSEQ * KVW + (size_t)h * LSEQ * HD;

    auto issue_kv_body = [&](int stage, int jt) {
        const uint32_t so = sb + 2 * QSM_B + (uint32_t)stage * FSTAGE;
        const int j0 = jt * 64;
        const __nv_bfloat16* srcs[4] = {g_Kh, g_Kl, g_Vh, g_Vl};
        #pragma unroll
        for (int t = 0; t < 4; t++) {
            #pragma unroll
            for (int k = 0; k < 2; k++) {
                int c = tid + k * 256;
                int row = c >> 3, cx = c & 7;
                uint32_t dst = so + (uint32_t)t * FKV_TILE + row * FTROW + cx * 16;
                CPASYNC(dst, srcs[t] + kbase + (size_t)(j0 + row) * HD + cx * 8);
            }
        }
    };

    // prologue: group 0 = Q(hi/lo) + KV0; group 1 = KV1
    {
        #pragma unroll
        for (int v = 0; v < 2; v++) {
            const __nv_bfloat16* src = v ? g_Ql : g_Qh;
            #pragma unroll
            for (int i = 0; i < 4; i++) {
                int c = tid + i * 256;
                int row = c >> 3, cx = c & 7;
                uint32_t dst = sb + (uint32_t)v * QSM_B + row * FTROW + cx * 16;
                CPASYNC(dst, src + qbase + (size_t)(q0 + row) * HD + cx * 8);
            }
        }
        issue_kv_body(0, 0);
        CPCOMMIT();
        if (1 <= jmax) issue_kv_body(1, 1);
        CPCOMMIT();
    }

    const uint32_t aq = (lane & 7) + ((lane >> 3) & 1) * 8;
    const uint32_t ak = (lane >> 4) * 8;
    const uint32_t bq = (lane & 7) + (lane >> 4) * 8;
    const uint32_t bk = ((lane >> 3) & 1) * 8;

    bool qloaded = false;
    uint32_t qhf[4][4], qlf[4][4];

    float of[8][4];
    #pragma unroll
    for (int a = 0; a < 8; a++)
        #pragma unroll
        for (int e = 0; e < 4; e++) of[a][e] = 0.f;
    float m_i[2] = {-1e30f, -1e30f}, l_i[2] = {0.f, 0.f};

    for (int jt = 0; jt <= jmax; jt++) {
        CPWAIT(1);
        __syncthreads();   // single barrier per tile

        if (!qloaded) {    // Q arrived with group 0
            #pragma unroll
            for (int ks = 0; ks < 4; ks++) {
                uint32_t addr = sb + (wm * 16 + aq) * FTROW + (ks * 16 + ak) * 2;
                ldm4(qhf[ks], addr);
                ldm4(qlf[ks], addr + QSM_B);
            }
            qloaded = true;
        }

        const bool skip = (q0 + wm * 16 + 15) < jt * 64;
        if (!skip) {
            const uint32_t so = sb + 2 * QSM_B + (uint32_t)(jt % FA_STAGES) * FSTAGE;

            // ---- S = Q K^T (base-2 logits; Q pre-scaled) ----
            float sf[8][4];
            #pragma unroll
            for (int a = 0; a < 8; a++)
                #pragma unroll
                for (int e = 0; e < 4; e++) sf[a][e] = 0.f;

            #pragma unroll
            for (int ks = 0; ks < 4; ks++) {
                #pragma unroll
                for (int nb = 0; nb < 4; nb++) {
                    uint32_t addr = so + (nb * 16 + bq) * FTROW + (ks * 16 + bk) * 2;
                    uint32_t rh[4], rl[4];
                    ldm4(rh, addr);
                    ldm4(rl, addr + FKV_TILE);
                    mma16816(sf[2*nb],   qhf[ks], &rh[0]);
                    mma16816(sf[2*nb],   qhf[ks], &rl[0]);
                    mma16816(sf[2*nb],   qlf[ks], &rh[0]);
                    mma16816(sf[2*nb+1], qhf[ks], &rh[2]);
                    mma16816(sf[2*nb+1], qhf[ks], &rl[2]);
                    mma16816(sf[2*nb+1], qlf[ks], &rh[2]);
                }
            }

            // ---- online softmax (base 2) per row-half ----
            #pragma unroll
            for (int hh = 0; hh < 2; hh++) {
                const int grow = q0 + wm * 16 + hh * 8 + g;
                float mx = -1e30f;
                #pragma unroll
                for (int a = 0; a < 8; a++)
                    #pragma unroll
                    for (int e = 0; e < 2; e++) {
                        int col = jt * 64 + a * 8 + 2 * tg + e;
                        float v = sf[a][2*hh + e];
                        if (col > grow) v = -1e30f;
                        sf[a][2*hh + e] = v;
                        mx = fmaxf(mx, v);
                    }
                mx = fmaxf(mx, __shfl_xor_sync(0xffffffffu, mx, 1));
                mx = fmaxf(mx, __shfl_xor_sync(0xffffffffu, mx, 2));
                const float mnew  = fmaxf(m_i[hh], mx);
                const float alpha = exp2p(m_i[hh] - mnew);
                float rs = 0.f;
                #pragma unroll
                for (int a = 0; a < 8; a++)
                    #pragma unroll
                    for (int e = 0; e < 2; e++) {
                        float p = exp2p(sf[a][2*hh + e] - mnew);
                        sf[a][2*hh + e] = p;
                        rs += p;
                    }
                rs += __shfl_xor_sync(0xffffffffu, rs, 1);
                rs += __shfl_xor_sync(0xffffffffu, rs, 2);
                l_i[hh] = l_i[hh] * alpha + rs;
                m_i[hh] = mnew;
                #pragma unroll
                for (int a = 0; a < 8; a++)
                    #pragma unroll
                    for (int e = 0; e < 2; e++) of[a][2*hh + e] *= alpha;
            }

            // ---- O += P V (P repacked C->A in registers, hi/lo split) ----
            #pragma unroll
            for (int ks = 0; ks < 4; ks++) {
                uint32_t pah[4], pal[4];
                #pragma unroll
                for (int q = 0; q < 4; q++) {
                    float p0 = sf[2*ks + (q >> 1)][(q & 1) * 2 + 0];
                    float p1 = sf[2*ks + (q >> 1)][(q & 1) * 2 + 1];
                    __nv_bfloat16 h0 = __float2bfloat16(p0);
                    __nv_bfloat16 h1 = __float2bfloat16(p1);
                    __nv_bfloat162 hp; hp.x = h0; hp.y = h1;
                    pah[q] = *(uint32_t*)&hp;
                    pal[q] = packbf(p0 - __bfloat162float(h0), p1 - __bfloat162float(h1));
                }

                #pragma unroll
                for (int nb = 0; nb < 4; nb++) {
                    uint32_t addr = so + 2 * FKV_TILE + (ks * 16 + aq) * FTROW + (nb * 16 + ak) * 2;
                    uint32_t rh[4], rl[4];
                    ldm4t(rh, addr);
                    ldm4t(rl, addr + FKV_TILE);
                    mma16816(of[2*nb],   pah, &rh[0]);
                    mma16816(of[2*nb],   pah, &rl[0]);
                    mma16816(of[2*nb],   pal, &rh[0]);
                    mma16816(of[2*nb+1], pah, &rh[2]);
                    mma16816(of[2*nb+1], pah, &rl[2]);
                    mma16816(of[2*nb+1], pal, &rh[2]);
                }
            }
        }

        // prefetch KV(jt+2) into the stage consumed at iter jt-1 (barrier-safe)
        if (jt + 2 <= jmax) issue_kv_body((jt + 2) % FA_STAGES, jt + 2);
        CPCOMMIT();   // committed every iter (empty at tail) to keep group math exact
    }

    // ---- epilogue: normalize, split to bf16 hi/lo, write AO (standard layout) ----
    const size_t aobase = (size_t)b * LSEQ * DMODEL;
    #pragma unroll
    for (int hh = 0; hh < 2; hh++) {
        const float inv = 1.f / l_i[hh];
        const int row = q0 + wm * 16 + hh * 8 + g;
        #pragma unroll
        for (int a = 0; a < 8; a++) {
            float o0 = of[a][2*hh + 0] * inv;
            float o1 = of[a][2*hh + 1] * inv;
            __nv_bfloat16 h0 = __float2bfloat16(o0);
            __nv_bfloat16 h1 = __float2bfloat16(o1);
            __nv_bfloat162 hp; hp.x = h0; hp.y = h1;
            size_t off = aobase + (size_t)row * DMODEL + gh * HD + a * 8 + 2 * tg;
            *(uint32_t*)(g_aoh + off) = *(uint32_t*)&hp;
            *(uint32_t*)(g_aol + off) = packbf(o0 - __bfloat162float(h0), o1 - __bfloat162float(h1));
        }
    }
}

// ===================== Launch =====================
extern "C" void kernel_launch(void* const* d_in, const int* in_sizes, int n_in,
                              void* d_out, int out_size)
{
    const float* x    = (const float*)d_in[0];   // (2, 2048, 2048)
    const float* Wqkv = (const float*)d_in[2];   // (2048, 3072)
    const float* Wout = (const float*)d_in[3];   // (2048, 2048)
    float* out = (float*)d_out;                  // (2, 2048, 2048)

    (void)cudaFuncSetAttribute(gemm_mma<1>,
                               cudaFuncAttributeMaxDynamicSharedMemorySize, GSMEM);
    (void)cudaFuncSetAttribute(gemm_mma<0>,
                               cudaFuncAttributeMaxDynamicSharedMemorySize, GSMEM);
    (void)cudaFuncSetAttribute(fa_mma,
                               cudaFuncAttributeMaxDynamicSharedMemorySize, FA_SMEM);

    const int n4 = MROWS * DMODEL / 4;

    split_convert<<<(n4 + 255) / 256, 256>>>(x, n4);
    transpose_convert<<<dim3(NQKV / 32, DMODEL / 32), dim3(32, 8)>>>(Wqkv, NQKV, 0);
    transpose_convert<<<dim3(DMODEL / 32, DMODEL / 32), dim3(32, 8)>>>(Wout, DMODEL, 1);

    gemm_mma<1><<<dim3(NQKV / 128, MROWS / 128), 256, GSMEM>>>(nullptr);
    fa_mma<<<dim3(LSEQ / 128, 32, NB), FA_T, FA_SMEM>>>();
    gemm_mma<0><<<dim3(DMODEL / 128, MROWS / 128), 256, GSMEM>>>(out);
}

// round 11
// speedup vs baseline: 1.0365x; 1.0365x over previous
#include <cuda_runtime.h>
#include <cuda_bf16.h>
#include <cstdint>

// Problem constants
#define LSEQ   2048
#define NB     2
#define DMODEL 2048
#define NQKV   3072
#define KVW    512
#define HD     64
#define MROWS  (NB * LSEQ)   // 4096

#define QSCALE 0.18033688011f   // 0.125 * log2(e): folded into Q at projection epilogue

// ---------------- scratch (device globals; no allocation allowed) ----------------
__device__ __nv_bfloat16 g_xh [MROWS * DMODEL], g_xl [MROWS * DMODEL];
__device__ __nv_bfloat16 g_aoh[MROWS * DMODEL], g_aol[MROWS * DMODEL];
__device__ __nv_bfloat16 g_wqh[NQKV * DMODEL],  g_wql[NQKV * DMODEL];    // W_qkv^T (N,K)
__device__ __nv_bfloat16 g_woh[DMODEL * DMODEL], g_wol[DMODEL * DMODEL]; // W_out^T (N,K)
// Q/K/V bf16 hi/lo. Plain-reshape semantics: head gh's Q is the CONTIGUOUS
// (LSEQ, 64) slab at gh*LSEQ*HD (row stride 64); K/V head h at h*LSEQ*HD.
__device__ __nv_bfloat16 g_Qh[MROWS * DMODEL], g_Ql[MROWS * DMODEL];
__device__ __nv_bfloat16 g_Kh[MROWS * KVW],    g_Kl[MROWS * KVW];
__device__ __nv_bfloat16 g_Vh[MROWS * KVW],    g_Vl[MROWS * KVW];

// ---------------- PTX helpers (portable ISA: sm_80+) ----------------
__device__ __forceinline__ uint32_t s2u(const void* p) {
    uint32_t a;
    asm("{ .reg .u64 t; cvta.to.shared.u64 t, %1; cvt.u32.u64 %0, t; }" : "=r"(a) : "l"(p));
    return a;
}

__device__ __forceinline__ void ldm4(uint32_t* r, uint32_t addr) {
    asm volatile("ldmatrix.sync.aligned.m8n8.x4.shared.b16 {%0,%1,%2,%3}, [%4];"
                 : "=r"(r[0]), "=r"(r[1]), "=r"(r[2]), "=r"(r[3]) : "r"(addr));
}
__device__ __forceinline__ void ldm4t(uint32_t* r, uint32_t addr) {
    asm volatile("ldmatrix.sync.aligned.m8n8.x4.trans.shared.b16 {%0,%1,%2,%3}, [%4];"
                 : "=r"(r[0]), "=r"(r[1]), "=r"(r[2]), "=r"(r[3]) : "r"(addr));
}

__device__ __forceinline__ void mma16816(float* d, const uint32_t* a, const uint32_t* b) {
    asm volatile("mma.sync.aligned.m16n8k16.row.col.f32.bf16.bf16.f32 "
                 "{%0,%1,%2,%3}, {%4,%5,%6,%7}, {%8,%9}, {%0,%1,%2,%3};"
                 : "+f"(d[0]), "+f"(d[1]), "+f"(d[2]), "+f"(d[3])
                 : "r"(a[0]), "r"(a[1]), "r"(a[2]), "r"(a[3]), "r"(b[0]), "r"(b[1]));
}

#define CPASYNC(dst, src) \
    asm volatile("cp.async.cg.shared.global [%0], [%1], 16;" :: "r"(dst), "l"(src))
#define CPCOMMIT() asm volatile("cp.async.commit_group;")
#define CPWAIT(n)  asm volatile("cp.async.wait_group %0;" :: "n"(n))

__device__ __forceinline__ uint32_t packbf(float lo_, float hi_) {
    __nv_bfloat162 t;
    t.x = __float2bfloat16(lo_);
    t.y = __float2bfloat16(hi_);
    return *(uint32_t*)&t;
}

// fast exp2 for t <= 0 (degree-6, rel err ~1.2e-5), FMA-pipe only
__device__ __forceinline__ float exp2p(float t) {
    t = fmaxf(t, -126.0f);
    float fl = floorf(t);
    float f  = t - fl;
    float p  = 1.5403530e-4f;
    p = p * f + 1.3333558e-3f;
    p = p * f + 9.6181291e-3f;
    p = p * f + 5.5504109e-2f;
    p = p * f + 2.4022651e-1f;
    p = p * f + 6.9314718e-1f;
    p = p * f + 1.0f;
    int i = (int)fl;
    return p * __int_as_float((uint32_t)(i + 127) << 23);
}

// ---------------- conversion kernels ----------------
__global__ void split_convert(const float* __restrict__ src, int n4)
{
    int i = blockIdx.x * blockDim.x + threadIdx.x;
    if (i >= n4) return;
    float4 v = ((const float4*)src)[i];
    float f[4] = {v.x, v.y, v.z, v.w};
    __nv_bfloat16 h[4], l[4];
    #pragma unroll
    for (int j = 0; j < 4; j++) {
        h[j] = __float2bfloat16(f[j]);
        l[j] = __float2bfloat16(f[j] - __bfloat162float(h[j]));
    }
    *(uint2*)(g_xh + 4 * (size_t)i) = *(uint2*)h;
    *(uint2*)(g_xl + 4 * (size_t)i) = *(uint2*)l;
}

__global__ void transpose_convert(const float* __restrict__ in, int N, int sel)
{
    __shared__ float t[32][33];
    __nv_bfloat16* hi = sel ? g_woh : g_wqh;
    __nv_bfloat16* lo = sel ? g_wol : g_wql;
    const int n0 = blockIdx.x * 32, k0 = blockIdx.y * 32;
    const int tx = threadIdx.x, ty = threadIdx.y;
    #pragma unroll
    for (int j = 0; j < 32; j += 8)
        t[ty + j][tx] = in[(size_t)(k0 + ty + j) * N + n0 + tx];
    __syncthreads();
    #pragma unroll
    for (int j = 0; j < 32; j += 8) {
        float v = t[tx][ty + j];
        int n = n0 + ty + j, k = k0 + tx;
        __nv_bfloat16 h = __float2bfloat16(v);
        hi[(size_t)n * DMODEL + k] = h;
        lo[(size_t)n * DMODEL + k] = __float2bfloat16(v - __bfloat162float(h));
    }
}

// ---------------- mma.sync bf16x3 GEMM: 128x128 block, K=2048, 2-stage (R8) ----------------
#define BKC 32
#define TROW 80                       // smem bytes per 32-bf16 row (ldmatrix conflict-free)
#define TILE_BYTES (128 * TROW)
#define STAGE_BYTES (4 * TILE_BYTES)
#define GSMEM (2 * STAGE_BYTES)       // 81920 -> 2 CTAs/SM
#define NCHUNK (DMODEL / BKC)         // 64

template<int MODE>
__global__ void __launch_bounds__(256)
gemm_mma(float* __restrict__ Cout)
{
    extern __shared__ char smem[];
    const uint32_t sb = s2u(smem);
    const int tid = threadIdx.x, wid = tid >> 5, lane = tid & 31;
    const int wm = wid >> 1, wn = wid & 1;

    const __nv_bfloat16 *Ah, *Al, *Bh, *Bl;
    if (MODE == 1) { Ah = g_xh;  Al = g_xl;  Bh = g_wqh; Bl = g_wql; }
    else           { Ah = g_aoh; Al = g_aol; Bh = g_woh; Bl = g_wol; }

    const int bm = blockIdx.y * 128;
    const int bn = blockIdx.x * 128;

    float acc[2][8][4];
    #pragma unroll
    for (int i = 0; i < 2; i++)
        #pragma unroll
        for (int j = 0; j < 8; j++)
            #pragma unroll
            for (int q = 0; q < 4; q++) acc[i][j][q] = 0.f;

    const int lrow0 = tid >> 2;
    const int lck   = tid & 3;

    auto issue_load = [&](int stage, int c) {
        const uint32_t so = sb + (uint32_t)stage * STAGE_BYTES;
        const int kc = c * BKC;
        const __nv_bfloat16* srcs[4] = {Ah, Al, Bh, Bl};
        #pragma unroll
        for (int t = 0; t < 4; t++) {
            const int rb = (t < 2) ? bm : bn;
            const __nv_bfloat16* s = srcs[t];
            #pragma unroll
            for (int half = 0; half < 2; half++) {
                int row = lrow0 + half * 64;
                uint32_t dst = so + (uint32_t)t * TILE_BYTES + row * TROW + lck * 16;
                const void* src = s + (size_t)(rb + row) * DMODEL + kc + lck * 8;
                CPASYNC(dst, src);
            }
        }
        CPCOMMIT();
    };

    issue_load(0, 0);

    const uint32_t aq = (lane & 7) + ((lane >> 3) & 1) * 8;
    const uint32_t ak = (lane >> 4) * 8;
    const uint32_t bq = (lane & 7) + (lane >> 4) * 8;
    const uint32_t bk = ((lane >> 3) & 1) * 8;

    for (int c = 0; c < NCHUNK; c++) {
        if (c + 1 < NCHUNK) issue_load((c + 1) & 1, c + 1);
        if (c + 1 < NCHUNK) { CPWAIT(1); } else { CPWAIT(0); }
        __syncthreads();

        const uint32_t so = sb + (uint32_t)(c & 1) * STAGE_BYTES;

        #pragma unroll
        for (int ks = 0; ks < 2; ks++) {
            uint32_t afh[2][4], afl[2][4];
            #pragma unroll
            for (int i = 0; i < 2; i++) {
                uint32_t addr = so + (wm * 32 + i * 16 + aq) * TROW + (ks * 16 + ak) * 2;
                ldm4(afh[i], addr);
                ldm4(afl[i], addr + TILE_BYTES);
            }
            uint32_t bfh[8][2], bfl[8][2];
            #pragma unroll
            for (int jj = 0; jj < 4; jj++) {
                uint32_t addr = so + 2 * TILE_BYTES
                              + (wn * 64 + jj * 16 + bq) * TROW + (ks * 16 + bk) * 2;
                uint32_t r[4];
                ldm4(r, addr);
                bfh[jj*2][0] = r[0]; bfh[jj*2][1] = r[1];
                bfh[jj*2+1][0] = r[2]; bfh[jj*2+1][1] = r[3];
                ldm4(r, addr + TILE_BYTES);
                bfl[jj*2][0] = r[0]; bfl[jj*2][1] = r[1];
                bfl[jj*2+1][0] = r[2]; bfl[jj*2+1][1] = r[3];
            }
            #pragma unroll
            for (int i = 0; i < 2; i++)
                #pragma unroll
                for (int j = 0; j < 8; j++) {
                    mma16816(acc[i][j], afh[i], bfh[j]);
                    mma16816(acc[i][j], afh[i], bfl[j]);
                    mma16816(acc[i][j], afl[i], bfh[j]);
                }
        }
        __syncthreads();
    }

    // ---- epilogue ----
    const int g = lane >> 2, tg = lane & 3;
    if (MODE == 0) {
        #pragma unroll
        for (int i = 0; i < 2; i++) {
            const int r0 = bm + wm * 32 + i * 16 + g;
            #pragma unroll
            for (int j = 0; j < 8; j++) {
                const int cc = bn + wn * 64 + j * 8 + tg * 2;
                *(float2*)(Cout + (size_t)r0 * DMODEL + cc)       = make_float2(acc[i][j][0], acc[i][j][1]);
                *(float2*)(Cout + (size_t)(r0 + 8) * DMODEL + cc) = make_float2(acc[i][j][2], acc[i][j][3]);
            }
        }
    } else {
        __nv_bfloat16 *dh, *dl; int ldd, c0; float scale;
        if (bn < DMODEL)            { dh = g_Qh; dl = g_Ql; ldd = DMODEL; c0 = bn;                scale = QSCALE; }
        else if (bn < DMODEL + KVW) { dh = g_Kh; dl = g_Kl; ldd = KVW;   c0 = bn - DMODEL;        scale = 1.f; }
        else                        { dh = g_Vh; dl = g_Vl; ldd = KVW;   c0 = bn - DMODEL - KVW;  scale = 1.f; }
        #pragma unroll
        for (int i = 0; i < 2; i++) {
            const int r0 = bm + wm * 32 + i * 16 + g;
            #pragma unroll
            for (int j = 0; j < 8; j++) {
                const int cc = c0 + wn * 64 + j * 8 + tg * 2;
                #pragma unroll
                for (int rr = 0; rr < 2; rr++) {
                    float v0 = acc[i][j][rr*2 + 0] * scale;
                    float v1 = acc[i][j][rr*2 + 1] * scale;
                    __nv_bfloat16 h0 = __float2bfloat16(v0);
                    __nv_bfloat16 h1 = __float2bfloat16(v1);
                    float l0 = v0 - __bfloat162float(h0);
                    float l1 = v1 - __bfloat162float(h1);
                    size_t off = (size_t)(r0 + rr * 8) * ldd + cc;
                    __nv_bfloat162 hp; hp.x = h0; hp.y = h1;
                    *(uint32_t*)(dh + off) = *(uint32_t*)&hp;
                    *(uint32_t*)(dl + off) = packbf(l0, l1);
                }
            }
        }
    }
}

// ---------------- flash attention, mma.sync bf16x3, Br=128 Bc=64, 2-stage ----------------
// 2 KV stages -> FA_SMEM 110592 -> 2 CTAs/SM (R10 lesson: occupancy > pipeline depth)
#define FA_T 256
#define FTROW 144                       // 64 bf16 = 128B data + 16B pad
#define QSM_B (128 * FTROW)             // 18432 per Q version
#define FKV_TILE (64 * FTROW)           // 9216
#define FSTAGE (4 * FKV_TILE)           // Kh,Kl,Vh,Vl = 36864
#define FA_SMEM (2 * QSM_B + 2 * FSTAGE)  // 110592

__global__ void __launch_bounds__(FA_T)
fa_mma()
{
    extern __shared__ char smem[];
    const uint32_t sb = s2u(smem);
    const int tid = threadIdx.x, wm = tid >> 5, lane = tid & 31;
    const int g = lane >> 2, tg = lane & 3;

    const int qt = blockIdx.x;
    const int gh = blockIdx.y;
    const int b  = blockIdx.z;
    const int h  = gh & 7;
    const int q0 = qt * 128;
    const int jmax = 2 * qt + 1;

    const size_t qbase = (size_t)b * LSEQ * DMODEL + (size_t)gh * LSEQ * HD;
    const size_t kbase = (size_t)b * LSEQ * KVW + (size_t)h * LSEQ * HD;

    auto issue_kv_body = [&](int stage, int jt) {
        const uint32_t so = sb + 2 * QSM_B + (uint32_t)stage * FSTAGE;
        const int j0 = jt * 64;
        const __nv_bfloat16* srcs[4] = {g_Kh, g_Kl, g_Vh, g_Vl};
        #pragma unroll
        for (int t = 0; t < 4; t++) {
            #pragma unroll
            for (int k = 0; k < 2; k++) {
                int c = tid + k * 256;
                int row = c >> 3, cx = c & 7;
                uint32_t dst = so + (uint32_t)t * FKV_TILE + row * FTROW + cx * 16;
                CPASYNC(dst, srcs[t] + kbase + (size_t)(j0 + row) * HD + cx * 8);
            }
        }
    };

    // prologue: group 0 = Q(hi/lo) + KV0 (stage 0); group 1 = KV1 (stage 1)
    {
        #pragma unroll
        for (int v = 0; v < 2; v++) {
            const __nv_bfloat16* src = v ? g_Ql : g_Qh;
            #pragma unroll
            for (int i = 0; i < 4; i++) {
                int c = tid + i * 256;
                int row = c >> 3, cx = c & 7;
                uint32_t dst = sb + (uint32_t)v * QSM_B + row * FTROW + cx * 16;
                CPASYNC(dst, src + qbase + (size_t)(q0 + row) * HD + cx * 8);
            }
        }
        issue_kv_body(0, 0);
        CPCOMMIT();
        if (1 <= jmax) issue_kv_body(1, 1);
        CPCOMMIT();
    }

    const uint32_t aq = (lane & 7) + ((lane >> 3) & 1) * 8;
    const uint32_t ak = (lane >> 4) * 8;
    const uint32_t bq = (lane & 7) + (lane >> 4) * 8;
    const uint32_t bk = ((lane >> 3) & 1) * 8;

    bool qloaded = false;
    uint32_t qhf[4][4], qlf[4][4];

    float of[8][4];
    #pragma unroll
    for (int a = 0; a < 8; a++)
        #pragma unroll
        for (int e = 0; e < 4; e++) of[a][e] = 0.f;
    float m_i[2] = {-1e30f, -1e30f}, l_i[2] = {0.f, 0.f};

    for (int jt = 0; jt <= jmax; jt++) {
        CPWAIT(1);            // group jt complete (group jt+1 may be in flight)
        __syncthreads();

        if (!qloaded) {       // Q arrived with group 0
            #pragma unroll
            for (int ks = 0; ks < 4; ks++) {
                uint32_t addr = sb + (wm * 16 + aq) * FTROW + (ks * 16 + ak) * 2;
                ldm4(qhf[ks], addr);
                ldm4(qlf[ks], addr + QSM_B);
            }
            qloaded = true;
        }

        const bool skip = (q0 + wm * 16 + 15) < jt * 64;
        if (!skip) {
            const uint32_t so = sb + 2 * QSM_B + (uint32_t)(jt & 1) * FSTAGE;

            // ---- S = Q K^T (base-2 logits; Q pre-scaled) ----
            float sf[8][4];
            #pragma unroll
            for (int a = 0; a < 8; a++)
                #pragma unroll
                for (int e = 0; e < 4; e++) sf[a][e] = 0.f;

            #pragma unroll
            for (int ks = 0; ks < 4; ks++) {
                #pragma unroll
                for (int nb = 0; nb < 4; nb++) {
                    uint32_t addr = so + (nb * 16 + bq) * FTROW + (ks * 16 + bk) * 2;
                    uint32_t rh[4], rl[4];
                    ldm4(rh, addr);
                    ldm4(rl, addr + FKV_TILE);
                    mma16816(sf[2*nb],   qhf[ks], &rh[0]);
                    mma16816(sf[2*nb],   qhf[ks], &rl[0]);
                    mma16816(sf[2*nb],   qlf[ks], &rh[0]);
                    mma16816(sf[2*nb+1], qhf[ks], &rh[2]);
                    mma16816(sf[2*nb+1], qhf[ks], &rl[2]);
                    mma16816(sf[2*nb+1], qlf[ks], &rh[2]);
                }
            }

            // ---- online softmax (base 2) per row-half ----
            #pragma unroll
            for (int hh = 0; hh < 2; hh++) {
                const int grow = q0 + wm * 16 + hh * 8 + g;
                float mx = -1e30f;
                #pragma unroll
                for (int a = 0; a < 8; a++)
                    #pragma unroll
                    for (int e = 0; e < 2; e++) {
                        int col = jt * 64 + a * 8 + 2 * tg + e;
                        float v = sf[a][2*hh + e];
                        if (col > grow) v = -1e30f;
                        sf[a][2*hh + e] = v;
                        mx = fmaxf(mx, v);
                    }
                mx = fmaxf(mx, __shfl_xor_sync(0xffffffffu, mx, 1));
                mx = fmaxf(mx, __shfl_xor_sync(0xffffffffu, mx, 2));
                const float mnew  = fmaxf(m_i[hh], mx);
                const float alpha = exp2p(m_i[hh] - mnew);
                float rs = 0.f;
                #pragma unroll
                for (int a = 0; a < 8; a++)
                    #pragma unroll
                    for (int e = 0; e < 2; e++) {
                        float p = exp2p(sf[a][2*hh + e] - mnew);
                        sf[a][2*hh + e] = p;
                        rs += p;
                    }
                rs += __shfl_xor_sync(0xffffffffu, rs, 1);
                rs += __shfl_xor_sync(0xffffffffu, rs, 2);
                l_i[hh] = l_i[hh] * alpha + rs;
                m_i[hh] = mnew;
                #pragma unroll
                for (int a = 0; a < 8; a++)
                    #pragma unroll
                    for (int e = 0; e < 2; e++) of[a][2*hh + e] *= alpha;
            }

            // ---- O += P V (P repacked C->A in registers, hi/lo split) ----
            #pragma unroll
            for (int ks = 0; ks < 4; ks++) {
                uint32_t pah[4], pal[4];
                #pragma unroll
                for (int q = 0; q < 4; q++) {
                    float p0 = sf[2*ks + (q >> 1)][(q & 1) * 2 + 0];
                    float p1 = sf[2*ks + (q >> 1)][(q & 1) * 2 + 1];
                    __nv_bfloat16 h0 = __float2bfloat16(p0);
                    __nv_bfloat16 h1 = __float2bfloat16(p1);
                    __nv_bfloat162 hp; hp.x = h0; hp.y = h1;
                    pah[q] = *(uint32_t*)&hp;
                    pal[q] = packbf(p0 - __bfloat162float(h0), p1 - __bfloat162float(h1));
                }

                #pragma unroll
                for (int nb = 0; nb < 4; nb++) {
                    uint32_t addr = so + 2 * FKV_TILE + (ks * 16 + aq) * FTROW + (nb * 16 + ak) * 2;
                    uint32_t rh[4], rl[4];
                    ldm4t(rh, addr);
                    ldm4t(rl, addr + FKV_TILE);
                    mma16816(of[2*nb],   pah, &rh[0]);
                    mma16816(of[2*nb],   pah, &rl[0]);
                    mma16816(of[2*nb],   pal, &rh[0]);
                    mma16816(of[2*nb+1], pah, &rh[2]);
                    mma16816(of[2*nb+1], pah, &rl[2]);
                    mma16816(of[2*nb+1], pal, &rh[2]);
                }
            }
        }
        __syncthreads();   // protect stage jt&1 before iter jt+1's prefetch overwrites it

        // prefetch KV(jt+2) into stage (jt+2)&1 == jt&1 (just finished reading)
        if (jt + 2 <= jmax) issue_kv_body((jt + 2) & 1, jt + 2);
        CPCOMMIT();        // committed every iter (empty at tail) to keep group math exact
    }

    // ---- epilogue: normalize, split to bf16 hi/lo, write AO (standard layout) ----
    const size_t aobase = (size_t)b * LSEQ * DMODEL;
    #pragma unroll
    for (int hh = 0; hh < 2; hh++) {
        const float inv = 1.f / l_i[hh];
        const int row = q0 + wm * 16 + hh * 8 + g;
        #pragma unroll
        for (int a = 0; a < 8; a++) {
            float o0 = of[a][2*hh + 0] * inv;
            float o1 = of[a][2*hh + 1] * inv;
            __nv_bfloat16 h0 = __float2bfloat16(o0);
            __nv_bfloat16 h1 = __float2bfloat16(o1);
            __nv_bfloat162 hp; hp.x = h0; hp.y = h1;
            size_t off = aobase + (size_t)row * DMODEL + gh * HD + a * 8 + 2 * tg;
            *(uint32_t*)(g_aoh + off) = *(uint32_t*)&hp;
            *(uint32_t*)(g_aol + off) = packbf(o0 - __bfloat162float(h0), o1 - __bfloat162float(h1));
        }
    }
}

// ===================== Launch =====================
extern "C" void kernel_launch(void* const* d_in, const int* in_sizes, int n_in,
                              void* d_out, int out_size)
{
    const float* x    = (const float*)d_in[0];   // (2, 2048, 2048)
    const float* Wqkv = (const float*)d_in[2];   // (2048, 3072)
    const float* Wout = (const float*)d_in[3];   // (2048, 2048)
    float* out = (float*)d_out;                  // (2, 2048, 2048)

    (void)cudaFuncSetAttribute(gemm_mma<1>,
                               cudaFuncAttributeMaxDynamicSharedMemorySize, GSMEM);
    (void)cudaFuncSetAttribute(gemm_mma<0>,
                               cudaFuncAttributeMaxDynamicSharedMemorySize, GSMEM);
    (void)cudaFuncSetAttribute(fa_mma,
                               cudaFuncAttributeMaxDynamicSharedMemorySize, FA_SMEM);

    const int n4 = MROWS * DMODEL / 4;

    split_convert<<<(n4 + 255) / 256, 256>>>(x, n4);
    transpose_convert<<<dim3(NQKV / 32, DMODEL / 32), dim3(32, 8)>>>(Wqkv, NQKV, 0);
    transpose_convert<<<dim3(DMODEL / 32, DMODEL / 32), dim3(32, 8)>>>(Wout, DMODEL, 1);

    gemm_mma<1><<<dim3(NQKV / 128, MROWS / 128), 256, GSMEM>>>(nullptr);
    fa_mma<<<dim3(LSEQ / 128, 32, NB), FA_T, FA_SMEM>>>();
    gemm_mma<0><<<dim3(DMODEL / 128, MROWS / 128), 256, GSMEM>>>(out);
}

// round 12
// speedup vs baseline: 1.1034x; 1.0646x over previous
#include <cuda_runtime.h>
#include <cuda_bf16.h>
#include <cstdint>

// Problem constants
#define LSEQ   2048
#define NB     2
#define DMODEL 2048
#define NQKV   3072
#define KVW    512
#define HD     64
#define MROWS  (NB * LSEQ)   // 4096

#define QSCALE 0.18033688011f   // 0.125 * log2(e): folded into Q at projection epilogue

// ---------------- scratch (device globals; no allocation allowed) ----------------
__device__ __nv_bfloat16 g_xh [MROWS * DMODEL], g_xl [MROWS * DMODEL];
__device__ __nv_bfloat16 g_aoh[MROWS * DMODEL], g_aol[MROWS * DMODEL];
__device__ __nv_bfloat16 g_wqh[NQKV * DMODEL],  g_wql[NQKV * DMODEL];    // W_qkv^T (N,K)
__device__ __nv_bfloat16 g_woh[DMODEL * DMODEL], g_wol[DMODEL * DMODEL]; // W_out^T (N,K)
// Q/K/V bf16 hi/lo. Plain-reshape semantics: head gh's Q is the CONTIGUOUS
// (LSEQ, 64) slab at gh*LSEQ*HD (row stride 64); K/V head h at h*LSEQ*HD.
__device__ __nv_bfloat16 g_Qh[MROWS * DMODEL], g_Ql[MROWS * DMODEL];
__device__ __nv_bfloat16 g_Kh[MROWS * KVW],    g_Kl[MROWS * KVW];
__device__ __nv_bfloat16 g_Vh[MROWS * KVW],    g_Vl[MROWS * KVW];

// ---------------- PTX helpers (portable ISA: sm_80+) ----------------
__device__ __forceinline__ uint32_t s2u(const void* p) {
    uint32_t a;
    asm("{ .reg .u64 t; cvta.to.shared.u64 t, %1; cvt.u32.u64 %0, t; }" : "=r"(a) : "l"(p));
    return a;
}

__device__ __forceinline__ void ldm4(uint32_t* r, uint32_t addr) {
    asm volatile("ldmatrix.sync.aligned.m8n8.x4.shared.b16 {%0,%1,%2,%3}, [%4];"
                 : "=r"(r[0]), "=r"(r[1]), "=r"(r[2]), "=r"(r[3]) : "r"(addr));
}
__device__ __forceinline__ void ldm4t(uint32_t* r, uint32_t addr) {
    asm volatile("ldmatrix.sync.aligned.m8n8.x4.trans.shared.b16 {%0,%1,%2,%3}, [%4];"
                 : "=r"(r[0]), "=r"(r[1]), "=r"(r[2]), "=r"(r[3]) : "r"(addr));
}

__device__ __forceinline__ void mma16816(float* d, const uint32_t* a, const uint32_t* b) {
    asm volatile("mma.sync.aligned.m16n8k16.row.col.f32.bf16.bf16.f32 "
                 "{%0,%1,%2,%3}, {%4,%5,%6,%7}, {%8,%9}, {%0,%1,%2,%3};"
                 : "+f"(d[0]), "+f"(d[1]), "+f"(d[2]), "+f"(d[3])
                 : "r"(a[0]), "r"(a[1]), "r"(a[2]), "r"(a[3]), "r"(b[0]), "r"(b[1]));
}

#define CPASYNC(dst, src) \
    asm volatile("cp.async.cg.shared.global [%0], [%1], 16;" :: "r"(dst), "l"(src))
#define CPCOMMIT() asm volatile("cp.async.commit_group;")
#define CPWAIT(n)  asm volatile("cp.async.wait_group %0;" :: "n"(n))

__device__ __forceinline__ uint32_t packbf(float lo_, float hi_) {
    __nv_bfloat162 t;
    t.x = __float2bfloat16(lo_);
    t.y = __float2bfloat16(hi_);
    return *(uint32_t*)&t;
}

// fast exp2 for t <= 0 (degree-6, rel err ~1.2e-5), FMA-pipe only
__device__ __forceinline__ float exp2p(float t) {
    t = fmaxf(t, -126.0f);
    float fl = floorf(t);
    float f  = t - fl;
    float p  = 1.5403530e-4f;
    p = p * f + 1.3333558e-3f;
    p = p * f + 9.6181291e-3f;
    p = p * f + 5.5504109e-2f;
    p = p * f + 2.4022651e-1f;
    p = p * f + 6.9314718e-1f;
    p = p * f + 1.0f;
    int i = (int)fl;
    return p * __int_as_float((uint32_t)(i + 127) << 23);
}

// ---------------- conversion kernels ----------------
__global__ void split_convert(const float* __restrict__ src, int n4)
{
    int i = blockIdx.x * blockDim.x + threadIdx.x;
    if (i >= n4) return;
    float4 v = ((const float4*)src)[i];
    float f[4] = {v.x, v.y, v.z, v.w};
    __nv_bfloat16 h[4], l[4];
    #pragma unroll
    for (int j = 0; j < 4; j++) {
        h[j] = __float2bfloat16(f[j]);
        l[j] = __float2bfloat16(f[j] - __bfloat162float(h[j]));
    }
    *(uint2*)(g_xh + 4 * (size_t)i) = *(uint2*)h;
    *(uint2*)(g_xl + 4 * (size_t)i) = *(uint2*)l;
}

__global__ void transpose_convert(const float* __restrict__ in, int N, int sel)
{
    __shared__ float t[32][33];
    __nv_bfloat16* hi = sel ? g_woh : g_wqh;
    __nv_bfloat16* lo = sel ? g_wol : g_wql;
    const int n0 = blockIdx.x * 32, k0 = blockIdx.y * 32;
    const int tx = threadIdx.x, ty = threadIdx.y;
    #pragma unroll
    for (int j = 0; j < 32; j += 8)
        t[ty + j][tx] = in[(size_t)(k0 + ty + j) * N + n0 + tx];
    __syncthreads();
    #pragma unroll
    for (int j = 0; j < 32; j += 8) {
        float v = t[tx][ty + j];
        int n = n0 + ty + j, k = k0 + tx;
        __nv_bfloat16 h = __float2bfloat16(v);
        hi[(size_t)n * DMODEL + k] = h;
        lo[(size_t)n * DMODEL + k] = __float2bfloat16(v - __bfloat162float(h));
    }
}

// -------- mma.sync bf16x3 GEMM: 128x256 CTA tile, 64x64 warp tiles, 3-stage --------
#define BKC 32
#define TROW 80                        // smem bytes per 32-bf16 row (ldmatrix conflict-free)
#define A_TILE (128 * TROW)            // 10240
#define B_TILE (256 * TROW)            // 20480
#define STAGE_BYTES (2 * A_TILE + 2 * B_TILE)  // 61440
#define GSTAGES 3
#define GSMEM (GSTAGES * STAGE_BYTES)  // 184320
#define NCHUNK (DMODEL / BKC)          // 64

// MODE 1: A=x, B=Wqkv^T; epilogue -> Qh/Ql (scaled), Kh/Kl, Vh/Vl
// MODE 0: A=AO(hi/lo), B=Wout^T; epilogue -> Cout fp32
template<int MODE>
__global__ void __launch_bounds__(256, 1)
gemm_mma(float* __restrict__ Cout)
{
    extern __shared__ char smem[];
    const uint32_t sb = s2u(smem);
    const int tid = threadIdx.x, wid = tid >> 5, lane = tid & 31;
    const int wm = wid >> 2, wn = wid & 3;   // 2 x 4 warp grid, warp tile 64x64

    const __nv_bfloat16 *Ah, *Al, *Bh, *Bl;
    if (MODE == 1) { Ah = g_xh;  Al = g_xl;  Bh = g_wqh; Bl = g_wql; }
    else           { Ah = g_aoh; Al = g_aol; Bh = g_woh; Bl = g_wol; }

    const int bm = blockIdx.y * 128;
    const int bn = blockIdx.x * 256;

    float acc[4][8][4];
    #pragma unroll
    for (int i = 0; i < 4; i++)
        #pragma unroll
        for (int j = 0; j < 8; j++)
            #pragma unroll
            for (int q = 0; q < 4; q++) acc[i][j][q] = 0.f;

    // loader coords: 4 sixteen-byte chunks per 64B row
    const int lrowA = tid >> 2;        // 0..63 (x2 halves -> 128 rows)
    const int lrowB = tid >> 2;        // 0..63 (x4 quarters -> 256 rows)
    const int lc16  = tid & 3;         // 0..3

    auto issue_load = [&](int stage, int c) {
        const uint32_t so = sb + (uint32_t)stage * STAGE_BYTES;
        const int kc = c * BKC;
        // A hi/lo: 128 rows
        #pragma unroll
        for (int t = 0; t < 2; t++) {
            const __nv_bfloat16* s = t ? Al : Ah;
            #pragma unroll
            for (int p = 0; p < 2; p++) {
                int row = lrowA + p * 64;
                uint32_t dst = so + (uint32_t)t * A_TILE + row * TROW + lc16 * 16;
                CPASYNC(dst, s + (size_t)(bm + row) * DMODEL + kc + lc16 * 8);
            }
        }
        // B hi/lo: 256 rows
        #pragma unroll
        for (int t = 0; t < 2; t++) {
            const __nv_bfloat16* s = t ? Bl : Bh;
            #pragma unroll
            for (int p = 0; p < 4; p++) {
                int row = lrowB + p * 64;
                uint32_t dst = so + 2 * A_TILE + (uint32_t)t * B_TILE + row * TROW + lc16 * 16;
                CPASYNC(dst, s + (size_t)(bn + row) * DMODEL + kc + lc16 * 8);
            }
        }
        CPCOMMIT();
    };

    issue_load(0, 0);
    issue_load(1, 1);

    const uint32_t aq = (lane & 7) + ((lane >> 3) & 1) * 8;
    const uint32_t ak = (lane >> 4) * 8;
    const uint32_t bq = (lane & 7) + (lane >> 4) * 8;
    const uint32_t bk = ((lane >> 3) & 1) * 8;

    for (int c = 0; c < NCHUNK; c++) {
        CPWAIT(1);
        __syncthreads();   // single barrier per chunk

        const uint32_t so = sb + (uint32_t)(c % GSTAGES) * STAGE_BYTES;

        #pragma unroll
        for (int ks = 0; ks < 2; ks++) {
            uint32_t afh[4][4], afl[4][4];
            #pragma unroll
            for (int i = 0; i < 4; i++) {
                uint32_t addr = so + (wm * 64 + i * 16 + aq) * TROW + (ks * 16 + ak) * 2;
                ldm4(afh[i], addr);
                ldm4(afl[i], addr + A_TILE);
            }
            #pragma unroll
            for (int jj = 0; jj < 4; jj++) {
                uint32_t addr = so + 2 * A_TILE
                              + (wn * 64 + jj * 16 + bq) * TROW + (ks * 16 + bk) * 2;
                uint32_t rh[4], rl[4];
                ldm4(rh, addr);
                ldm4(rl, addr + B_TILE);
                #pragma unroll
                for (int i = 0; i < 4; i++) {
                    mma16816(acc[i][jj*2],   afh[i], &rh[0]);
                    mma16816(acc[i][jj*2],   afh[i], &rl[0]);
                    mma16816(acc[i][jj*2],   afl[i], &rh[0]);
                    mma16816(acc[i][jj*2+1], afh[i], &rh[2]);
                    mma16816(acc[i][jj*2+1], afh[i], &rl[2]);
                    mma16816(acc[i][jj*2+1], afl[i], &rh[2]);
                }
            }
        }

        // prefetch chunk c+2 into stage (c+2)%3 == (c-1)%3 (read finished; barrier-proven)
        if (c + 2 < NCHUNK) issue_load((c + 2) % GSTAGES, c + 2);
        else                CPCOMMIT();   // empty group keeps wait_group math exact
    }

    // ---- epilogue ----
    const int g = lane >> 2, tg = lane & 3;
    if (MODE == 0) {
        #pragma unroll
        for (int i = 0; i < 4; i++) {
            const int r0 = bm + wm * 64 + i * 16 + g;
            #pragma unroll
            for (int j = 0; j < 8; j++) {
                const int cc = bn + wn * 64 + j * 8 + tg * 2;
                *(float2*)(Cout + (size_t)r0 * DMODEL + cc)       = make_float2(acc[i][j][0], acc[i][j][1]);
                *(float2*)(Cout + (size_t)(r0 + 8) * DMODEL + cc) = make_float2(acc[i][j][2], acc[i][j][3]);
            }
        }
    } else {
        // bn is a multiple of 256; regions [0,2048) Q, [2048,2560) K, [2560,3072) V
        // are unions of 256-blocks, so the target is block-uniform.
        __nv_bfloat16 *dh, *dl; int ldd, c0; float scale;
        if (bn < DMODEL)            { dh = g_Qh; dl = g_Ql; ldd = DMODEL; c0 = bn;                scale = QSCALE; }
        else if (bn < DMODEL + KVW) { dh = g_Kh; dl = g_Kl; ldd = KVW;   c0 = bn - DMODEL;        scale = 1.f; }
        else                        { dh = g_Vh; dl = g_Vl; ldd = KVW;   c0 = bn - DMODEL - KVW;  scale = 1.f; }
        #pragma unroll
        for (int i = 0; i < 4; i++) {
            const int r0 = bm + wm * 64 + i * 16 + g;
            #pragma unroll
            for (int j = 0; j < 8; j++) {
                const int cc = c0 + wn * 64 + j * 8 + tg * 2;
                #pragma unroll
                for (int rr = 0; rr < 2; rr++) {
                    float v0 = acc[i][j][rr*2 + 0] * scale;
                    float v1 = acc[i][j][rr*2 + 1] * scale;
                    __nv_bfloat16 h0 = __float2bfloat16(v0);
                    __nv_bfloat16 h1 = __float2bfloat16(v1);
                    float l0 = v0 - __bfloat162float(h0);
                    float l1 = v1 - __bfloat162float(h1);
                    size_t off = (size_t)(r0 + rr * 8) * ldd + cc;
                    __nv_bfloat162 hp; hp.x = h0; hp.y = h1;
                    *(uint32_t*)(dh + off) = *(uint32_t*)&hp;
                    *(uint32_t*)(dl + off) = packbf(l0, l1);
                }
            }
        }
    }
}

// ---------------- flash attention (verbatim 1330-µs version): Br=128 Bc=64, 2-stage ----------------
#define FA_T 256
#define FTROW 144                       // 64 bf16 = 128B data + 16B pad
#define QSM_B (128 * FTROW)             // 18432 per Q version
#define FKV_TILE (64 * FTROW)           // 9216
#define FSTAGE (4 * FKV_TILE)           // Kh,Kl,Vh,Vl = 36864
#define FA_SMEM (2 * QSM_B + 2 * FSTAGE) // 110592

__global__ void __launch_bounds__(FA_T)
fa_mma()
{
    extern __shared__ char smem[];
    const uint32_t sb = s2u(smem);
    const int tid = threadIdx.x, wm = tid >> 5, lane = tid & 31;
    const int g = lane >> 2, tg = lane & 3;

    const int qt = blockIdx.x;
    const int gh = blockIdx.y;
    const int b  = blockIdx.z;
    const int h  = gh & 7;
    const int q0 = qt * 128;
    const int jmax = 2 * qt + 1;

    const size_t qbase = (size_t)b * LSEQ * DMODEL + (size_t)gh * LSEQ * HD;
    const size_t kbase = (size_t)b * LSEQ * KVW + (size_t)h * LSEQ * HD;

    // ---- prologue: load Q (hi/lo) + KV stage 0 ----
    {
        #pragma unroll
        for (int v = 0; v < 2; v++) {
            const __nv_bfloat16* src = v ? g_Ql : g_Qh;
            #pragma unroll
            for (int i = 0; i < 4; i++) {
                int c = tid + i * 256;
                int row = c >> 3, cx = c & 7;
                uint32_t dst = sb + (uint32_t)v * QSM_B + row * FTROW + cx * 16;
                CPASYNC(dst, src + qbase + (size_t)(q0 + row) * HD + cx * 8);
            }
        }
        CPCOMMIT();
    }

    auto issue_kv = [&](int stage, int jt) {
        const uint32_t so = sb + 2 * QSM_B + (uint32_t)stage * FSTAGE;
        const int j0 = jt * 64;
        const __nv_bfloat16* srcs[4] = {g_Kh, g_Kl, g_Vh, g_Vl};
        #pragma unroll
        for (int t = 0; t < 4; t++) {
            #pragma unroll
            for (int k = 0; k < 2; k++) {
                int c = tid + k * 256;
                int row = c >> 3, cx = c & 7;
                uint32_t dst = so + (uint32_t)t * FKV_TILE + row * FTROW + cx * 16;
                CPASYNC(dst, srcs[t] + kbase + (size_t)(j0 + row) * HD + cx * 8);
            }
        }
        CPCOMMIT();
    };

    issue_kv(0, 0);
    CPWAIT(0);
    __syncthreads();

    // Q fragments (register-resident for the whole block)
    const uint32_t aq = (lane & 7) + ((lane >> 3) & 1) * 8;
    const uint32_t ak = (lane >> 4) * 8;
    const uint32_t bq = (lane & 7) + (lane >> 4) * 8;
    const uint32_t bk = ((lane >> 3) & 1) * 8;

    uint32_t qhf[4][4], qlf[4][4];
    #pragma unroll
    for (int ks = 0; ks < 4; ks++) {
        uint32_t addr = sb + (wm * 16 + aq) * FTROW + (ks * 16 + ak) * 2;
        ldm4(qhf[ks], addr);
        ldm4(qlf[ks], addr + QSM_B);
    }

    float of[8][4];
    #pragma unroll
    for (int a = 0; a < 8; a++)
        #pragma unroll
        for (int e = 0; e < 4; e++) of[a][e] = 0.f;
    float m_i[2] = {-1e30f, -1e30f}, l_i[2] = {0.f, 0.f};

    for (int jt = 0; jt <= jmax; jt++) {
        if (jt + 1 <= jmax) { issue_kv((jt + 1) & 1, jt + 1); CPWAIT(1); }
        else                { CPWAIT(0); }
        __syncthreads();

        // fully-masked warps (first half at the odd diagonal tile) skip compute
        const bool skip = (q0 + wm * 16 + 15) < jt * 64;
        if (!skip) {
            const uint32_t so = sb + 2 * QSM_B + (uint32_t)(jt & 1) * FSTAGE;

            // ---- S = Q K^T (base-2 logits; Q pre-scaled) ----
            float sf[8][4];
            #pragma unroll
            for (int a = 0; a < 8; a++)
                #pragma unroll
                for (int e = 0; e < 4; e++) sf[a][e] = 0.f;

            #pragma unroll
            for (int ks = 0; ks < 4; ks++) {
                #pragma unroll
                for (int nb = 0; nb < 4; nb++) {
                    uint32_t addr = so + (nb * 16 + bq) * FTROW + (ks * 16 + bk) * 2;
                    uint32_t rh[4], rl[4];
                    ldm4(rh, addr);
                    ldm4(rl, addr + FKV_TILE);
                    mma16816(sf[2*nb],   qhf[ks], &rh[0]);
                    mma16816(sf[2*nb],   qhf[ks], &rl[0]);
                    mma16816(sf[2*nb],   qlf[ks], &rh[0]);
                    mma16816(sf[2*nb+1], qhf[ks], &rh[2]);
                    mma16816(sf[2*nb+1], qhf[ks], &rl[2]);
                    mma16816(sf[2*nb+1], qlf[ks], &rh[2]);
                }
            }

            // ---- online softmax (base 2) per row-half ----
            #pragma unroll
            for (int hh = 0; hh < 2; hh++) {
                const int grow = q0 + wm * 16 + hh * 8 + g;
                float mx = -1e30f;
                #pragma unroll
                for (int a = 0; a < 8; a++)
                    #pragma unroll
                    for (int e = 0; e < 2; e++) {
                        int col = jt * 64 + a * 8 + 2 * tg + e;
                        float v = sf[a][2*hh + e];
                        if (col > grow) v = -1e30f;
                        sf[a][2*hh + e] = v;
                        mx = fmaxf(mx, v);
                    }
                mx = fmaxf(mx, __shfl_xor_sync(0xffffffffu, mx, 1));
                mx = fmaxf(mx, __shfl_xor_sync(0xffffffffu, mx, 2));
                const float mnew  = fmaxf(m_i[hh], mx);
                const float alpha = exp2p(m_i[hh] - mnew);
                float rs = 0.f;
                #pragma unroll
                for (int a = 0; a < 8; a++)
                    #pragma unroll
                    for (int e = 0; e < 2; e++) {
                        float p = exp2p(sf[a][2*hh + e] - mnew);
                        sf[a][2*hh + e] = p;
                        rs += p;
                    }
                rs += __shfl_xor_sync(0xffffffffu, rs, 1);
                rs += __shfl_xor_sync(0xffffffffu, rs, 2);
                l_i[hh] = l_i[hh] * alpha + rs;
                m_i[hh] = mnew;
                #pragma unroll
                for (int a = 0; a < 8; a++)
                    #pragma unroll
                    for (int e = 0; e < 2; e++) of[a][2*hh + e] *= alpha;
            }

            // ---- O += P V (P repacked C->A in registers, hi/lo split) ----
            #pragma unroll
            for (int ks = 0; ks < 4; ks++) {
                uint32_t pah[4], pal[4];
                #pragma unroll
                for (int q = 0; q < 4; q++) {
                    float p0 = sf[2*ks + (q >> 1)][(q & 1) * 2 + 0];
                    float p1 = sf[2*ks + (q >> 1)][(q & 1) * 2 + 1];
                    __nv_bfloat16 h0 = __float2bfloat16(p0);
                    __nv_bfloat16 h1 = __float2bfloat16(p1);
                    __nv_bfloat162 hp; hp.x = h0; hp.y = h1;
                    pah[q] = *(uint32_t*)&hp;
                    pal[q] = packbf(p0 - __bfloat162float(h0), p1 - __bfloat162float(h1));
                }

                #pragma unroll
                for (int nb = 0; nb < 4; nb++) {
                    uint32_t addr = so + 2 * FKV_TILE + (ks * 16 + aq) * FTROW + (nb * 16 + ak) * 2;
                    uint32_t rh[4], rl[4];
                    ldm4t(rh, addr);
                    ldm4t(rl, addr + FKV_TILE);
                    mma16816(of[2*nb],   pah, &rh[0]);
                    mma16816(of[2*nb],   pah, &rl[0]);
                    mma16816(of[2*nb],   pal, &rh[0]);
                    mma16816(of[2*nb+1], pah, &rh[2]);
                    mma16816(of[2*nb+1], pah, &rl[2]);
                    mma16816(of[2*nb+1], pal, &rh[2]);
                }
            }
        }
        __syncthreads();
    }

    // ---- epilogue: normalize, split to bf16 hi/lo, write AO (standard layout) ----
    const size_t aobase = (size_t)b * LSEQ * DMODEL;
    #pragma unroll
    for (int hh = 0; hh < 2; hh++) {
        const float inv = 1.f / l_i[hh];
        const int row = q0 + wm * 16 + hh * 8 + g;
        #pragma unroll
        for (int a = 0; a < 8; a++) {
            float o0 = of[a][2*hh + 0] * inv;
            float o1 = of[a][2*hh + 1] * inv;
            __nv_bfloat16 h0 = __float2bfloat16(o0);
            __nv_bfloat16 h1 = __float2bfloat16(o1);
            __nv_bfloat162 hp; hp.x = h0; hp.y = h1;
            size_t off = aobase + (size_t)row * DMODEL + gh * HD + a * 8 + 2 * tg;
            *(uint32_t*)(g_aoh + off) = *(uint32_t*)&hp;
            *(uint32_t*)(g_aol + off) = packbf(o0 - __bfloat162float(h0), o1 - __bfloat162float(h1));
        }
    }
}

// ===================== Launch =====================
extern "C" void kernel_launch(void* const* d_in, const int* in_sizes, int n_in,
                              void* d_out, int out_size)
{
    const float* x    = (const float*)d_in[0];   // (2, 2048, 2048)
    const float* Wqkv = (const float*)d_in[2];   // (2048, 3072)
    const float* Wout = (const float*)d_in[3];   // (2048, 2048)
    float* out = (float*)d_out;                  // (2, 2048, 2048)

    (void)cudaFuncSetAttribute(gemm_mma<1>,
                               cudaFuncAttributeMaxDynamicSharedMemorySize, GSMEM);
    (void)cudaFuncSetAttribute(gemm_mma<0>,
                               cudaFuncAttributeMaxDynamicSharedMemorySize, GSMEM);
    (void)cudaFuncSetAttribute(fa_mma,
                               cudaFuncAttributeMaxDynamicSharedMemorySize, FA_SMEM);

    const int n4 = MROWS * DMODEL / 4;

    split_convert<<<(n4 + 255) / 256, 256>>>(x, n4);
    transpose_convert<<<dim3(NQKV / 32, DMODEL / 32), dim3(32, 8)>>>(Wqkv, NQKV, 0);
    transpose_convert<<<dim3(DMODEL / 32, DMODEL / 32), dim3(32, 8)>>>(Wout, DMODEL, 1);

    gemm_mma<1><<<dim3(NQKV / 256, MROWS / 128), 256, GSMEM>>>(nullptr);
    fa_mma<<<dim3(LSEQ / 128, 32, NB), FA_T, FA_SMEM>>>();
    gemm_mma<0><<<dim3(DMODEL / 256, MROWS / 128), 256, GSMEM>>>(out);
}

// round 13
// speedup vs baseline: 1.1055x; 1.0019x over previous
#include <cuda_runtime.h>
#include <cuda_bf16.h>
#include <cstdint>

// Problem constants
#define LSEQ   2048
#define NB     2
#define DMODEL 2048
#define NQKV   3072
#define KVW    512
#define HD     64
#define MROWS  (NB * LSEQ)   // 4096

#define QSCALE 0.18033688011f   // 0.125 * log2(e): folded into Q at projection epilogue

// ---------------- scratch (device globals; no allocation allowed) ----------------
__device__ __nv_bfloat16 g_xh [MROWS * DMODEL], g_xl [MROWS * DMODEL];
__device__ __nv_bfloat16 g_aoh[MROWS * DMODEL], g_aol[MROWS * DMODEL];
__device__ __nv_bfloat16 g_wqh[NQKV * DMODEL],  g_wql[NQKV * DMODEL];    // W_qkv^T (N,K)
__device__ __nv_bfloat16 g_woh[DMODEL * DMODEL], g_wol[DMODEL * DMODEL]; // W_out^T (N,K)
// Q/K/V bf16 hi/lo. Plain-reshape semantics: head gh's Q is the CONTIGUOUS
// (LSEQ, 64) slab at gh*LSEQ*HD (row stride 64); K/V head h at h*LSEQ*HD.
__device__ __nv_bfloat16 g_Qh[MROWS * DMODEL], g_Ql[MROWS * DMODEL];
__device__ __nv_bfloat16 g_Kh[MROWS * KVW],    g_Kl[MROWS * KVW];
__device__ __nv_bfloat16 g_Vh[MROWS * KVW],    g_Vl[MROWS * KVW];

// ---------------- PTX helpers (portable ISA: sm_80+) ----------------
__device__ __forceinline__ uint32_t s2u(const void* p) {
    uint32_t a;
    asm("{ .reg .u64 t; cvta.to.shared.u64 t, %1; cvt.u32.u64 %0, t; }" : "=r"(a) : "l"(p));
    return a;
}

__device__ __forceinline__ void ldm4(uint32_t* r, uint32_t addr) {
    asm volatile("ldmatrix.sync.aligned.m8n8.x4.shared.b16 {%0,%1,%2,%3}, [%4];"
                 : "=r"(r[0]), "=r"(r[1]), "=r"(r[2]), "=r"(r[3]) : "r"(addr));
}
__device__ __forceinline__ void ldm4t(uint32_t* r, uint32_t addr) {
    asm volatile("ldmatrix.sync.aligned.m8n8.x4.trans.shared.b16 {%0,%1,%2,%3}, [%4];"
                 : "=r"(r[0]), "=r"(r[1]), "=r"(r[2]), "=r"(r[3]) : "r"(addr));
}

__device__ __forceinline__ void mma16816(float* d, const uint32_t* a, const uint32_t* b) {
    asm volatile("mma.sync.aligned.m16n8k16.row.col.f32.bf16.bf16.f32 "
                 "{%0,%1,%2,%3}, {%4,%5,%6,%7}, {%8,%9}, {%0,%1,%2,%3};"
                 : "+f"(d[0]), "+f"(d[1]), "+f"(d[2]), "+f"(d[3])
                 : "r"(a[0]), "r"(a[1]), "r"(a[2]), "r"(a[3]), "r"(b[0]), "r"(b[1]));
}

#define CPASYNC(dst, src) \
    asm volatile("cp.async.cg.shared.global [%0], [%1], 16;" :: "r"(dst), "l"(src))
#define CPCOMMIT() asm volatile("cp.async.commit_group;")
#define CPWAIT(n)  asm volatile("cp.async.wait_group %0;" :: "n"(n))

__device__ __forceinline__ uint32_t packbf(float lo_, float hi_) {
    __nv_bfloat162 t;
    t.x = __float2bfloat16(lo_);
    t.y = __float2bfloat16(hi_);
    return *(uint32_t*)&t;
}

// fast exp2 for t <= 0 (degree-6, rel err ~1.2e-5), FMA-pipe only
__device__ __forceinline__ float exp2p(float t) {
    t = fmaxf(t, -126.0f);
    float fl = floorf(t);
    float f  = t - fl;
    float p  = 1.5403530e-4f;
    p = p * f + 1.3333558e-3f;
    p = p * f + 9.6181291e-3f;
    p = p * f + 5.5504109e-2f;
    p = p * f + 2.4022651e-1f;
    p = p * f + 6.9314718e-1f;
    p = p * f + 1.0f;
    int i = (int)fl;
    return p * __int_as_float((uint32_t)(i + 127) << 23);
}

// ---------------- conversion kernels ----------------
__global__ void split_convert(const float* __restrict__ src, int n4)
{
    int i = blockIdx.x * blockDim.x + threadIdx.x;
    if (i >= n4) return;
    float4 v = ((const float4*)src)[i];
    float f[4] = {v.x, v.y, v.z, v.w};
    __nv_bfloat16 h[4], l[4];
    #pragma unroll
    for (int j = 0; j < 4; j++) {
        h[j] = __float2bfloat16(f[j]);
        l[j] = __float2bfloat16(f[j] - __bfloat162float(h[j]));
    }
    *(uint2*)(g_xh + 4 * (size_t)i) = *(uint2*)h;
    *(uint2*)(g_xl + 4 * (size_t)i) = *(uint2*)l;
}

__global__ void transpose_convert(const float* __restrict__ in, int N, int sel)
{
    __shared__ float t[32][33];
    __nv_bfloat16* hi = sel ? g_woh : g_wqh;
    __nv_bfloat16* lo = sel ? g_wol : g_wql;
    const int n0 = blockIdx.x * 32, k0 = blockIdx.y * 32;
    const int tx = threadIdx.x, ty = threadIdx.y;
    #pragma unroll
    for (int j = 0; j < 32; j += 8)
        t[ty + j][tx] = in[(size_t)(k0 + ty + j) * N + n0 + tx];
    __syncthreads();
    #pragma unroll
    for (int j = 0; j < 32; j += 8) {
        float v = t[tx][ty + j];
        int n = n0 + ty + j, k = k0 + tx;
        __nv_bfloat16 h = __float2bfloat16(v);
        hi[(size_t)n * DMODEL + k] = h;
        lo[(size_t)n * DMODEL + k] = __float2bfloat16(v - __bfloat162float(h));
    }
}

// -------- mma.sync bf16x3 GEMM: 128x256 CTA tile, 64x64 warp tiles, 3-stage --------
#define BKC 32
#define TROW 80                        // smem bytes per 32-bf16 row (ldmatrix conflict-free)
#define A_TILE (128 * TROW)            // 10240
#define B_TILE (256 * TROW)            // 20480
#define STAGE_BYTES (2 * A_TILE + 2 * B_TILE)  // 61440
#define GSTAGES 3
#define GSMEM (GSTAGES * STAGE_BYTES)  // 184320
#define NCHUNK (DMODEL / BKC)          // 64

// MODE 1: A=x, B=Wqkv^T; epilogue -> Qh/Ql (scaled), Kh/Kl, Vh/Vl
// MODE 0: A=AO(hi/lo), B=Wout^T; epilogue -> Cout fp32
template<int MODE>
__global__ void __launch_bounds__(256, 1)
gemm_mma(float* __restrict__ Cout)
{
    extern __shared__ char smem[];
    const uint32_t sb = s2u(smem);
    const int tid = threadIdx.x, wid = tid >> 5, lane = tid & 31;
    const int wm = wid >> 2, wn = wid & 3;   // 2 x 4 warp grid, warp tile 64x64

    const __nv_bfloat16 *Ah, *Al, *Bh, *Bl;
    if (MODE == 1) { Ah = g_xh;  Al = g_xl;  Bh = g_wqh; Bl = g_wql; }
    else           { Ah = g_aoh; Al = g_aol; Bh = g_woh; Bl = g_wol; }

    const int bm = blockIdx.y * 128;
    const int bn = blockIdx.x * 256;

    float acc[4][8][4];
    #pragma unroll
    for (int i = 0; i < 4; i++)
        #pragma unroll
        for (int j = 0; j < 8; j++)
            #pragma unroll
            for (int q = 0; q < 4; q++) acc[i][j][q] = 0.f;

    // loader coords: 4 sixteen-byte chunks per 64B row
    const int lrowA = tid >> 2;        // 0..63 (x2 halves -> 128 rows)
    const int lrowB = tid >> 2;        // 0..63 (x4 quarters -> 256 rows)
    const int lc16  = tid & 3;         // 0..3

    auto issue_load = [&](int stage, int c) {
        const uint32_t so = sb + (uint32_t)stage * STAGE_BYTES;
        const int kc = c * BKC;
        // A hi/lo: 128 rows
        #pragma unroll
        for (int t = 0; t < 2; t++) {
            const __nv_bfloat16* s = t ? Al : Ah;
            #pragma unroll
            for (int p = 0; p < 2; p++) {
                int row = lrowA + p * 64;
                uint32_t dst = so + (uint32_t)t * A_TILE + row * TROW + lc16 * 16;
                CPASYNC(dst, s + (size_t)(bm + row) * DMODEL + kc + lc16 * 8);
            }
        }
        // B hi/lo: 256 rows
        #pragma unroll
        for (int t = 0; t < 2; t++) {
            const __nv_bfloat16* s = t ? Bl : Bh;
            #pragma unroll
            for (int p = 0; p < 4; p++) {
                int row = lrowB + p * 64;
                uint32_t dst = so + 2 * A_TILE + (uint32_t)t * B_TILE + row * TROW + lc16 * 16;
                CPASYNC(dst, s + (size_t)(bn + row) * DMODEL + kc + lc16 * 8);
            }
        }
        CPCOMMIT();
    };

    issue_load(0, 0);
    issue_load(1, 1);

    const uint32_t aq = (lane & 7) + ((lane >> 3) & 1) * 8;
    const uint32_t ak = (lane >> 4) * 8;
    const uint32_t bq = (lane & 7) + (lane >> 4) * 8;
    const uint32_t bk = ((lane >> 3) & 1) * 8;

    for (int c = 0; c < NCHUNK; c++) {
        CPWAIT(1);
        __syncthreads();   // single barrier per chunk

        const uint32_t so = sb + (uint32_t)(c % GSTAGES) * STAGE_BYTES;

        #pragma unroll
        for (int ks = 0; ks < 2; ks++) {
            uint32_t afh[4][4], afl[4][4];
            #pragma unroll
            for (int i = 0; i < 4; i++) {
                uint32_t addr = so + (wm * 64 + i * 16 + aq) * TROW + (ks * 16 + ak) * 2;
                ldm4(afh[i], addr);
                ldm4(afl[i], addr + A_TILE);
            }
            #pragma unroll
            for (int jj = 0; jj < 4; jj++) {
                uint32_t addr = so + 2 * A_TILE
                              + (wn * 64 + jj * 16 + bq) * TROW + (ks * 16 + bk) * 2;
                uint32_t rh[4], rl[4];
                ldm4(rh, addr);
                ldm4(rl, addr + B_TILE);
                // Pass-major MMA order: all 8 accumulators get pass 0, then pass 1,
                // then pass 2 -> per-acc RAW dependency distance 8 (was 1).
                // Per-acc accumulation order unchanged (hh, hl, lh): bit-identical.
                #pragma unroll
                for (int pass = 0; pass < 3; pass++) {
                    const uint32_t* bsel = (pass == 1) ? rl : rh;
                    #pragma unroll
                    for (int i = 0; i < 4; i++)
                        mma16816(acc[i][jj*2],   (pass == 2) ? afl[i] : afh[i], &bsel[0]);
                    #pragma unroll
                    for (int i = 0; i < 4; i++)
                        mma16816(acc[i][jj*2+1], (pass == 2) ? afl[i] : afh[i], &bsel[2]);
                }
            }
        }

        // prefetch chunk c+2 into stage (c+2)%3 == (c-1)%3 (read finished; barrier-proven)
        if (c + 2 < NCHUNK) issue_load((c + 2) % GSTAGES, c + 2);
        else                CPCOMMIT();   // empty group keeps wait_group math exact
    }

    // ---- epilogue ----
    const int g = lane >> 2, tg = lane & 3;
    if (MODE == 0) {
        #pragma unroll
        for (int i = 0; i < 4; i++) {
            const int r0 = bm + wm * 64 + i * 16 + g;
            #pragma unroll
            for (int j = 0; j < 8; j++) {
                const int cc = bn + wn * 64 + j * 8 + tg * 2;
                *(float2*)(Cout + (size_t)r0 * DMODEL + cc)       = make_float2(acc[i][j][0], acc[i][j][1]);
                *(float2*)(Cout + (size_t)(r0 + 8) * DMODEL + cc) = make_float2(acc[i][j][2], acc[i][j][3]);
            }
        }
    } else {
        // bn is a multiple of 256; regions Q/K/V are unions of 256-blocks (block-uniform).
        __nv_bfloat16 *dh, *dl; int ldd, c0; float scale;
        if (bn < DMODEL)            { dh = g_Qh; dl = g_Ql; ldd = DMODEL; c0 = bn;                scale = QSCALE; }
        else if (bn < DMODEL + KVW) { dh = g_Kh; dl = g_Kl; ldd = KVW;   c0 = bn - DMODEL;        scale = 1.f; }
        else                        { dh = g_Vh; dl = g_Vl; ldd = KVW;   c0 = bn - DMODEL - KVW;  scale = 1.f; }
        #pragma unroll
        for (int i = 0; i < 4; i++) {
            const int r0 = bm + wm * 64 + i * 16 + g;
            #pragma unroll
            for (int j = 0; j < 8; j++) {
                const int cc = c0 + wn * 64 + j * 8 + tg * 2;
                #pragma unroll
                for (int rr = 0; rr < 2; rr++) {
                    float v0 = acc[i][j][rr*2 + 0] * scale;
                    float v1 = acc[i][j][rr*2 + 1] * scale;
                    __nv_bfloat16 h0 = __float2bfloat16(v0);
                    __nv_bfloat16 h1 = __float2bfloat16(v1);
                    float l0 = v0 - __bfloat162float(h0);
                    float l1 = v1 - __bfloat162float(h1);
                    size_t off = (size_t)(r0 + rr * 8) * ldd + cc;
                    __nv_bfloat162 hp; hp.x = h0; hp.y = h1;
                    *(uint32_t*)(dh + off) = *(uint32_t*)&hp;
                    *(uint32_t*)(dl + off) = packbf(l0, l1);
                }
            }
        }
    }
}

// ---------------- flash attention: Br=128 Bc=64, 2-stage (1330-µs base + MMA reorder) ----------------
#define FA_T 256
#define FTROW 144                       // 64 bf16 = 128B data + 16B pad
#define QSM_B (128 * FTROW)             // 18432 per Q version
#define FKV_TILE (64 * FTROW)           // 9216
#define FSTAGE (4 * FKV_TILE)           // Kh,Kl,Vh,Vl = 36864
#define FA_SMEM (2 * QSM_B + 2 * FSTAGE) // 110592

__global__ void __launch_bounds__(FA_T)
fa_mma()
{
    extern __shared__ char smem[];
    const uint32_t sb = s2u(smem);
    const int tid = threadIdx.x, wm = tid >> 5, lane = tid & 31;
    const int g = lane >> 2, tg = lane & 3;

    const int qt = blockIdx.x;
    const int gh = blockIdx.y;
    const int b  = blockIdx.z;
    const int h  = gh & 7;
    const int q0 = qt * 128;
    const int jmax = 2 * qt + 1;

    const size_t qbase = (size_t)b * LSEQ * DMODEL + (size_t)gh * LSEQ * HD;
    const size_t kbase = (size_t)b * LSEQ * KVW + (size_t)h * LSEQ * HD;

    // ---- prologue: load Q (hi/lo) + KV stage 0 ----
    {
        #pragma unroll
        for (int v = 0; v < 2; v++) {
            const __nv_bfloat16* src = v ? g_Ql : g_Qh;
            #pragma unroll
            for (int i = 0; i < 4; i++) {
                int c = tid + i * 256;
                int row = c >> 3, cx = c & 7;
                uint32_t dst = sb + (uint32_t)v * QSM_B + row * FTROW + cx * 16;
                CPASYNC(dst, src + qbase + (size_t)(q0 + row) * HD + cx * 8);
            }
        }
        CPCOMMIT();
    }

    auto issue_kv = [&](int stage, int jt) {
        const uint32_t so = sb + 2 * QSM_B + (uint32_t)stage * FSTAGE;
        const int j0 = jt * 64;
        const __nv_bfloat16* srcs[4] = {g_Kh, g_Kl, g_Vh, g_Vl};
        #pragma unroll
        for (int t = 0; t < 4; t++) {
            #pragma unroll
            for (int k = 0; k < 2; k++) {
                int c = tid + k * 256;
                int row = c >> 3, cx = c & 7;
                uint32_t dst = so + (uint32_t)t * FKV_TILE + row * FTROW + cx * 16;
                CPASYNC(dst, srcs[t] + kbase + (size_t)(j0 + row) * HD + cx * 8);
            }
        }
        CPCOMMIT();
    };

    issue_kv(0, 0);
    CPWAIT(0);
    __syncthreads();

    // Q fragments (register-resident for the whole block)
    const uint32_t aq = (lane & 7) + ((lane >> 3) & 1) * 8;
    const uint32_t ak = (lane >> 4) * 8;
    const uint32_t bq = (lane & 7) + (lane >> 4) * 8;
    const uint32_t bk = ((lane >> 3) & 1) * 8;

    uint32_t qhf[4][4], qlf[4][4];
    #pragma unroll
    for (int ks = 0; ks < 4; ks++) {
        uint32_t addr = sb + (wm * 16 + aq) * FTROW + (ks * 16 + ak) * 2;
        ldm4(qhf[ks], addr);
        ldm4(qlf[ks], addr + QSM_B);
    }

    float of[8][4];
    #pragma unroll
    for (int a = 0; a < 8; a++)
        #pragma unroll
        for (int e = 0; e < 4; e++) of[a][e] = 0.f;
    float m_i[2] = {-1e30f, -1e30f}, l_i[2] = {0.f, 0.f};

    for (int jt = 0; jt <= jmax; jt++) {
        if (jt + 1 <= jmax) { issue_kv((jt + 1) & 1, jt + 1); CPWAIT(1); }
        else                { CPWAIT(0); }
        __syncthreads();

        // fully-masked warps (first half at the odd diagonal tile) skip compute
        const bool skip = (q0 + wm * 16 + 15) < jt * 64;
        if (!skip) {
            const uint32_t so = sb + 2 * QSM_B + (uint32_t)(jt & 1) * FSTAGE;

            // ---- S = Q K^T (base-2 logits; Q pre-scaled) ----
            float sf[8][4];
            #pragma unroll
            for (int a = 0; a < 8; a++)
                #pragma unroll
                for (int e = 0; e < 4; e++) sf[a][e] = 0.f;

            #pragma unroll
            for (int ks = 0; ks < 4; ks++) {
                #pragma unroll
                for (int nb = 0; nb < 4; nb++) {
                    uint32_t addr = so + (nb * 16 + bq) * FTROW + (ks * 16 + bk) * 2;
                    uint32_t rh[4], rl[4];
                    ldm4(rh, addr);
                    ldm4(rl, addr + FKV_TILE);
                    // pass-major: per-acc dependency distance 2 (was 1); order hh,hl,lh kept
                    mma16816(sf[2*nb],   qhf[ks], &rh[0]);
                    mma16816(sf[2*nb+1], qhf[ks], &rh[2]);
                    mma16816(sf[2*nb],   qhf[ks], &rl[0]);
                    mma16816(sf[2*nb+1], qhf[ks], &rl[2]);
                    mma16816(sf[2*nb],   qlf[ks], &rh[0]);
                    mma16816(sf[2*nb+1], qlf[ks], &rh[2]);
                }
            }

            // ---- online softmax (base 2) per row-half ----
            #pragma unroll
            for (int hh = 0; hh < 2; hh++) {
                const int grow = q0 + wm * 16 + hh * 8 + g;
                float mx = -1e30f;
                #pragma unroll
                for (int a = 0; a < 8; a++)
                    #pragma unroll
                    for (int e = 0; e < 2; e++) {
                        int col = jt * 64 + a * 8 + 2 * tg + e;
                        float v = sf[a][2*hh + e];
                        if (col > grow) v = -1e30f;
                        sf[a][2*hh + e] = v;
                        mx = fmaxf(mx, v);
                    }
                mx = fmaxf(mx, __shfl_xor_sync(0xffffffffu, mx, 1));
                mx = fmaxf(mx, __shfl_xor_sync(0xffffffffu, mx, 2));
                const float mnew  = fmaxf(m_i[hh], mx);
                const float alpha = exp2p(m_i[hh] - mnew);
                float rs = 0.f;
                #pragma unroll
                for (int a = 0; a < 8; a++)
                    #pragma unroll
                    for (int e = 0; e < 2; e++) {
                        float p = exp2p(sf[a][2*hh + e] - mnew);
                        sf[a][2*hh + e] = p;
                        rs += p;
                    }
                rs += __shfl_xor_sync(0xffffffffu, rs, 1);
                rs += __shfl_xor_sync(0xffffffffu, rs, 2);
                l_i[hh] = l_i[hh] * alpha + rs;
                m_i[hh] = mnew;
                #pragma unroll
                for (int a = 0; a < 8; a++)
                    #pragma unroll
                    for (int e = 0; e < 2; e++) of[a][2*hh + e] *= alpha;
            }

            // ---- O += P V (P repacked C->A in registers, hi/lo split) ----
            #pragma unroll
            for (int ks = 0; ks < 4; ks++) {
                uint32_t pah[4], pal[4];
                #pragma unroll
                for (int q = 0; q < 4; q++) {
                    float p0 = sf[2*ks + (q >> 1)][(q & 1) * 2 + 0];
                    float p1 = sf[2*ks + (q >> 1)][(q & 1) * 2 + 1];
                    __nv_bfloat16 h0 = __float2bfloat16(p0);
                    __nv_bfloat16 h1 = __float2bfloat16(p1);
                    __nv_bfloat162 hp; hp.x = h0; hp.y = h1;
                    pah[q] = *(uint32_t*)&hp;
                    pal[q] = packbf(p0 - __bfloat162float(h0), p1 - __bfloat162float(h1));
                }

                #pragma unroll
                for (int nb = 0; nb < 4; nb++) {
                    uint32_t addr = so + 2 * FKV_TILE + (ks * 16 + aq) * FTROW + (nb * 16 + ak) * 2;
                    uint32_t rh[4], rl[4];
                    ldm4t(rh, addr);
                    ldm4t(rl, addr + FKV_TILE);
                    // pass-major: per-acc dependency distance 2; order hh,hl,lh kept
                    mma16816(of[2*nb],   pah, &rh[0]);
                    mma16816(of[2*nb+1], pah, &rh[2]);
                    mma16816(of[2*nb],   pah, &rl[0]);
                    mma16816(of[2*nb+1], pah, &rl[2]);
                    mma16816(of[2*nb],   pal, &rh[0]);
                    mma16816(of[2*nb+1], pal, &rh[2]);
                }
            }
        }
        __syncthreads();
    }

    // ---- epilogue: normalize, split to bf16 hi/lo, write AO (standard layout) ----
    const size_t aobase = (size_t)b * LSEQ * DMODEL;
    #pragma unroll
    for (int hh = 0; hh < 2; hh++) {
        const float inv = 1.f / l_i[hh];
        const int row = q0 + wm * 16 + hh * 8 + g;
        #pragma unroll
        for (int a = 0; a < 8; a++) {
            float o0 = of[a][2*hh + 0] * inv;
            float o1 = of[a][2*hh + 1] * inv;
            __nv_bfloat16 h0 = __float2bfloat16(o0);
            __nv_bfloat16 h1 = __float2bfloat16(o1);
            __nv_bfloat162 hp; hp.x = h0; hp.y = h1;
            size_t off = aobase + (size_t)row * DMODEL + gh * HD + a * 8 + 2 * tg;
            *(uint32_t*)(g_aoh + off) = *(uint32_t*)&hp;
            *(uint32_t*)(g_aol + off) = packbf(o0 - __bfloat162float(h0), o1 - __bfloat162float(h1));
        }
    }
}

// ===================== Launch =====================
extern "C" void kernel_launch(void* const* d_in, const int* in_sizes, int n_in,
                              void* d_out, int out_size)
{
    const float* x    = (const float*)d_in[0];   // (2, 2048, 2048)
    const float* Wqkv = (const float*)d_in[2];   // (2048, 3072)
    const float* Wout = (const float*)d_in[3];   // (2048, 2048)
    float* out = (float*)d_out;                  // (2, 2048, 2048)

    (void)cudaFuncSetAttribute(gemm_mma<1>,
                               cudaFuncAttributeMaxDynamicSharedMemorySize, GSMEM);
    (void)cudaFuncSetAttribute(gemm_mma<0>,
                               cudaFuncAttributeMaxDynamicSharedMemorySize, GSMEM);
    (void)cudaFuncSetAttribute(fa_mma,
                               cudaFuncAttributeMaxDynamicSharedMemorySize, FA_SMEM);

    const int n4 = MROWS * DMODEL / 4;

    split_convert<<<(n4 + 255) / 256, 256>>>(x, n4);
    transpose_convert<<<dim3(NQKV / 32, DMODEL / 32), dim3(32, 8)>>>(Wqkv, NQKV, 0);
    transpose_convert<<<dim3(DMODEL / 32, DMODEL / 32), dim3(32, 8)>>>(Wout, DMODEL, 1);

    gemm_mma<1><<<dim3(NQKV / 256, MROWS / 128), 256, GSMEM>>>(nullptr);
    fa_mma<<<dim3(LSEQ / 128, 32, NB), FA_T, FA_SMEM>>>();
    gemm_mma<0><<<dim3(DMODEL / 256, MROWS / 128), 256, GSMEM>>>(out);
}

// round 14
// speedup vs baseline: 1.1571x; 1.0467x over previous
#include <cuda_runtime.h>
#include <cuda_bf16.h>
#include <cstdint>

// Problem constants
#define LSEQ   2048
#define NB     2
#define DMODEL 2048
#define NQKV   3072
#define KVW    512
#define HD     64
#define MROWS  (NB * LSEQ)   // 4096

#define QSCALE 0.18033688011f   // 0.125 * log2(e): folded into Q at projection epilogue

// ---------------- scratch (device globals; no allocation allowed) ----------------
__device__ __nv_bfloat16 g_xh [MROWS * DMODEL], g_xl [MROWS * DMODEL];
__device__ __nv_bfloat16 g_aoh[MROWS * DMODEL], g_aol[MROWS * DMODEL];
__device__ __nv_bfloat16 g_wqh[NQKV * DMODEL],  g_wql[NQKV * DMODEL];    // W_qkv^T (N,K)
__device__ __nv_bfloat16 g_woh[DMODEL * DMODEL], g_wol[DMODEL * DMODEL]; // W_out^T (N,K)
// Q/K/V bf16 hi/lo. Plain-reshape semantics: head gh's Q is the CONTIGUOUS
// (LSEQ, 64) slab at gh*LSEQ*HD (row stride 64); K/V head h at h*LSEQ*HD.
__device__ __nv_bfloat16 g_Qh[MROWS * DMODEL], g_Ql[MROWS * DMODEL];
__device__ __nv_bfloat16 g_Kh[MROWS * KVW],    g_Kl[MROWS * KVW];
__device__ __nv_bfloat16 g_Vh[MROWS * KVW],    g_Vl[MROWS * KVW];

// ---------------- PTX helpers (portable ISA: sm_80+) ----------------
__device__ __forceinline__ uint32_t s2u(const void* p) {
    uint32_t a;
    asm("{ .reg .u64 t; cvta.to.shared.u64 t, %1; cvt.u32.u64 %0, t; }" : "=r"(a) : "l"(p));
    return a;
}

__device__ __forceinline__ void ldm4(uint32_t* r, uint32_t addr) {
    asm volatile("ldmatrix.sync.aligned.m8n8.x4.shared.b16 {%0,%1,%2,%3}, [%4];"
                 : "=r"(r[0]), "=r"(r[1]), "=r"(r[2]), "=r"(r[3]) : "r"(addr));
}
__device__ __forceinline__ void ldm4t(uint32_t* r, uint32_t addr) {
    asm volatile("ldmatrix.sync.aligned.m8n8.x4.trans.shared.b16 {%0,%1,%2,%3}, [%4];"
                 : "=r"(r[0]), "=r"(r[1]), "=r"(r[2]), "=r"(r[3]) : "r"(addr));
}

__device__ __forceinline__ void mma16816(float* d, const uint32_t* a, const uint32_t* b) {
    asm volatile("mma.sync.aligned.m16n8k16.row.col.f32.bf16.bf16.f32 "
                 "{%0,%1,%2,%3}, {%4,%5,%6,%7}, {%8,%9}, {%0,%1,%2,%3};"
                 : "+f"(d[0]), "+f"(d[1]), "+f"(d[2]), "+f"(d[3])
                 : "r"(a[0]), "r"(a[1]), "r"(a[2]), "r"(a[3]), "r"(b[0]), "r"(b[1]));
}

#define CPASYNC(dst, src) \
    asm volatile("cp.async.cg.shared.global [%0], [%1], 16;" :: "r"(dst), "l"(src))
#define CPCOMMIT() asm volatile("cp.async.commit_group;")
#define CPWAIT(n)  asm volatile("cp.async.wait_group %0;" :: "n"(n))

__device__ __forceinline__ uint32_t packbf(float lo_, float hi_) {
    __nv_bfloat162 t;
    t.x = __float2bfloat16(lo_);
    t.y = __float2bfloat16(hi_);
    return *(uint32_t*)&t;
}

// fast exp2 for t <= 0 (degree-6, rel err ~1.2e-5), FMA-pipe only
__device__ __forceinline__ float exp2p(float t) {
    t = fmaxf(t, -126.0f);
    float fl = floorf(t);
    float f  = t - fl;
    float p  = 1.5403530e-4f;
    p = p * f + 1.3333558e-3f;
    p = p * f + 9.6181291e-3f;
    p = p * f + 5.5504109e-2f;
    p = p * f + 2.4022651e-1f;
    p = p * f + 6.9314718e-1f;
    p = p * f + 1.0f;
    int i = (int)fl;
    return p * __int_as_float((uint32_t)(i + 127) << 23);
}

// ---------------- conversion kernels ----------------
__global__ void split_convert(const float* __restrict__ src, int n4)
{
    int i = blockIdx.x * blockDim.x + threadIdx.x;
    if (i >= n4) return;
    float4 v = ((const float4*)src)[i];
    float f[4] = {v.x, v.y, v.z, v.w};
    __nv_bfloat16 h[4], l[4];
    #pragma unroll
    for (int j = 0; j < 4; j++) {
        h[j] = __float2bfloat16(f[j]);
        l[j] = __float2bfloat16(f[j] - __bfloat162float(h[j]));
    }
    *(uint2*)(g_xh + 4 * (size_t)i) = *(uint2*)h;
    *(uint2*)(g_xl + 4 * (size_t)i) = *(uint2*)l;
}

__global__ void transpose_convert(const float* __restrict__ in, int N, int sel)
{
    __shared__ float t[32][33];
    __nv_bfloat16* hi = sel ? g_woh : g_wqh;
    __nv_bfloat16* lo = sel ? g_wol : g_wql;
    const int n0 = blockIdx.x * 32, k0 = blockIdx.y * 32;
    const int tx = threadIdx.x, ty = threadIdx.y;
    #pragma unroll
    for (int j = 0; j < 32; j += 8)
        t[ty + j][tx] = in[(size_t)(k0 + ty + j) * N + n0 + tx];
    __syncthreads();
    #pragma unroll
    for (int j = 0; j < 32; j += 8) {
        float v = t[tx][ty + j];
        int n = n0 + ty + j, k = k0 + tx;
        __nv_bfloat16 h = __float2bfloat16(v);
        hi[(size_t)n * DMODEL + k] = h;
        lo[(size_t)n * DMODEL + k] = __float2bfloat16(v - __bfloat162float(h));
    }
}

// -------- mma.sync bf16x3 GEMM: 128x256 CTA tile, 16 warps (32x64 warp tile), 3-stage --------
#define BKC 32
#define TROW 80                        // smem bytes per 32-bf16 row (ldmatrix conflict-free)
#define A_TILE (128 * TROW)            // 10240
#define B_TILE (256 * TROW)            // 20480
#define STAGE_BYTES (2 * A_TILE + 2 * B_TILE)  // 61440
#define GSTAGES 3
#define GSMEM (GSTAGES * STAGE_BYTES)  // 184320
#define NCHUNK (DMODEL / BKC)          // 64
#define GEMM_T 512

// MODE 1: A=x, B=Wqkv^T; epilogue -> Qh/Ql (scaled), Kh/Kl, Vh/Vl
// MODE 0: A=AO(hi/lo), B=Wout^T; epilogue -> Cout fp32
template<int MODE>
__global__ void __launch_bounds__(GEMM_T, 1)
gemm_mma(float* __restrict__ Cout)
{
    extern __shared__ char smem[];
    const uint32_t sb = s2u(smem);
    const int tid = threadIdx.x, wid = tid >> 5, lane = tid & 31;
    const int wm = wid >> 2, wn = wid & 3;   // 4 x 4 warp grid, warp tile 32x64

    const __nv_bfloat16 *Ah, *Al, *Bh, *Bl;
    if (MODE == 1) { Ah = g_xh;  Al = g_xl;  Bh = g_wqh; Bl = g_wql; }
    else           { Ah = g_aoh; Al = g_aol; Bh = g_woh; Bl = g_wol; }

    const int bm = blockIdx.y * 128;
    const int bn = blockIdx.x * 256;

    float acc[2][8][4];
    #pragma unroll
    for (int i = 0; i < 2; i++)
        #pragma unroll
        for (int j = 0; j < 8; j++)
            #pragma unroll
            for (int q = 0; q < 4; q++) acc[i][j][q] = 0.f;

    // loader coords: 512 threads; 4 sixteen-byte chunks per 64B row
    const int lrow = tid >> 2;         // 0..127
    const int lc16 = tid & 3;          // 0..3

    auto issue_load = [&](int stage, int c) {
        const uint32_t so = sb + (uint32_t)stage * STAGE_BYTES;
        const int kc = c * BKC;
        // A hi/lo: 128 rows (one row per thread-group)
        #pragma unroll
        for (int t = 0; t < 2; t++) {
            const __nv_bfloat16* s = t ? Al : Ah;
            uint32_t dst = so + (uint32_t)t * A_TILE + lrow * TROW + lc16 * 16;
            CPASYNC(dst, s + (size_t)(bm + lrow) * DMODEL + kc + lc16 * 8);
        }
        // B hi/lo: 256 rows
        #pragma unroll
        for (int t = 0; t < 2; t++) {
            const __nv_bfloat16* s = t ? Bl : Bh;
            #pragma unroll
            for (int p = 0; p < 2; p++) {
                int row = lrow + p * 128;
                uint32_t dst = so + 2 * A_TILE + (uint32_t)t * B_TILE + row * TROW + lc16 * 16;
                CPASYNC(dst, s + (size_t)(bn + row) * DMODEL + kc + lc16 * 8);
            }
        }
        CPCOMMIT();
    };

    issue_load(0, 0);
    issue_load(1, 1);

    const uint32_t aq = (lane & 7) + ((lane >> 3) & 1) * 8;
    const uint32_t ak = (lane >> 4) * 8;
    const uint32_t bq = (lane & 7) + (lane >> 4) * 8;
    const uint32_t bk = ((lane >> 3) & 1) * 8;

    for (int c = 0; c < NCHUNK; c++) {
        CPWAIT(1);
        __syncthreads();   // single barrier per chunk

        const uint32_t so = sb + (uint32_t)(c % GSTAGES) * STAGE_BYTES;

        #pragma unroll
        for (int ks = 0; ks < 2; ks++) {
            uint32_t afh[2][4], afl[2][4];
            #pragma unroll
            for (int i = 0; i < 2; i++) {
                uint32_t addr = so + (wm * 32 + i * 16 + aq) * TROW + (ks * 16 + ak) * 2;
                ldm4(afh[i], addr);
                ldm4(afl[i], addr + A_TILE);
            }
            #pragma unroll
            for (int jj = 0; jj < 4; jj++) {
                uint32_t addr = so + 2 * A_TILE
                              + (wn * 64 + jj * 16 + bq) * TROW + (ks * 16 + bk) * 2;
                uint32_t rh[4], rl[4];
                ldm4(rh, addr);
                ldm4(rl, addr + B_TILE);
                // per-acc order hh, hl, lh (bit-identical accumulation)
                #pragma unroll
                for (int pass = 0; pass < 3; pass++) {
                    const uint32_t* bsel = (pass == 1) ? rl : rh;
                    #pragma unroll
                    for (int i = 0; i < 2; i++)
                        mma16816(acc[i][jj*2],   (pass == 2) ? afl[i] : afh[i], &bsel[0]);
                    #pragma unroll
                    for (int i = 0; i < 2; i++)
                        mma16816(acc[i][jj*2+1], (pass == 2) ? afl[i] : afh[i], &bsel[2]);
                }
            }
        }

        // prefetch chunk c+2 into stage (c+2)%3 == (c-1)%3 (read finished; barrier-proven)
        if (c + 2 < NCHUNK) issue_load((c + 2) % GSTAGES, c + 2);
        else                CPCOMMIT();   // empty group keeps wait_group math exact
    }

    // ---- epilogue ----
    const int g = lane >> 2, tg = lane & 3;
    if (MODE == 0) {
        #pragma unroll
        for (int i = 0; i < 2; i++) {
            const int r0 = bm + wm * 32 + i * 16 + g;
            #pragma unroll
            for (int j = 0; j < 8; j++) {
                const int cc = bn + wn * 64 + j * 8 + tg * 2;
                *(float2*)(Cout + (size_t)r0 * DMODEL + cc)       = make_float2(acc[i][j][0], acc[i][j][1]);
                *(float2*)(Cout + (size_t)(r0 + 8) * DMODEL + cc) = make_float2(acc[i][j][2], acc[i][j][3]);
            }
        }
    } else {
        // bn is a multiple of 256; regions Q/K/V are unions of 256-blocks (block-uniform).
        __nv_bfloat16 *dh, *dl; int ldd, c0; float scale;
        if (bn < DMODEL)            { dh = g_Qh; dl = g_Ql; ldd = DMODEL; c0 = bn;                scale = QSCALE; }
        else if (bn < DMODEL + KVW) { dh = g_Kh; dl = g_Kl; ldd = KVW;   c0 = bn - DMODEL;        scale = 1.f; }
        else                        { dh = g_Vh; dl = g_Vl; ldd = KVW;   c0 = bn - DMODEL - KVW;  scale = 1.f; }
        #pragma unroll
        for (int i = 0; i < 2; i++) {
            const int r0 = bm + wm * 32 + i * 16 + g;
            #pragma unroll
            for (int j = 0; j < 8; j++) {
                const int cc = c0 + wn * 64 + j * 8 + tg * 2;
                #pragma unroll
                for (int rr = 0; rr < 2; rr++) {
                    float v0 = acc[i][j][rr*2 + 0] * scale;
                    float v1 = acc[i][j][rr*2 + 1] * scale;
                    __nv_bfloat16 h0 = __float2bfloat16(v0);
                    __nv_bfloat16 h1 = __float2bfloat16(v1);
                    float l0 = v0 - __bfloat162float(h0);
                    float l1 = v1 - __bfloat162float(h1);
                    size_t off = (size_t)(r0 + rr * 8) * ldd + cc;
                    __nv_bfloat162 hp; hp.x = h0; hp.y = h1;
                    *(uint32_t*)(dh + off) = *(uint32_t*)&hp;
                    *(uint32_t*)(dl + off) = packbf(l0, l1);
                }
            }
        }
    }
}

// ---------------- flash attention: Br=128 Bc=64, 2-stage (verbatim R13 1261-µs version) ----------------
#define FA_T 256
#define FTROW 144                       // 64 bf16 = 128B data + 16B pad
#define QSM_B (128 * FTROW)             // 18432 per Q version
#define FKV_TILE (64 * FTROW)           // 9216
#define FSTAGE (4 * FKV_TILE)           // Kh,Kl,Vh,Vl = 36864
#define FA_SMEM (2 * QSM_B + 2 * FSTAGE) // 110592

__global__ void __launch_bounds__(FA_T)
fa_mma()
{
    extern __shared__ char smem[];
    const uint32_t sb = s2u(smem);
    const int tid = threadIdx.x, wm = tid >> 5, lane = tid & 31;
    const int g = lane >> 2, tg = lane & 3;

    const int qt = blockIdx.x;
    const int gh = blockIdx.y;
    const int b  = blockIdx.z;
    const int h  = gh & 7;
    const int q0 = qt * 128;
    const int jmax = 2 * qt + 1;

    const size_t qbase = (size_t)b * LSEQ * DMODEL + (size_t)gh * LSEQ * HD;
    const size_t kbase = (size_t)b * LSEQ * KVW + (size_t)h * LSEQ * HD;

    // ---- prologue: load Q (hi/lo) + KV stage 0 ----
    {
        #pragma unroll
        for (int v = 0; v < 2; v++) {
            const __nv_bfloat16* src = v ? g_Ql : g_Qh;
            #pragma unroll
            for (int i = 0; i < 4; i++) {
                int c = tid + i * 256;
                int row = c >> 3, cx = c & 7;
                uint32_t dst = sb + (uint32_t)v * QSM_B + row * FTROW + cx * 16;
                CPASYNC(dst, src + qbase + (size_t)(q0 + row) * HD + cx * 8);
            }
        }
        CPCOMMIT();
    }

    auto issue_kv = [&](int stage, int jt) {
        const uint32_t so = sb + 2 * QSM_B + (uint32_t)stage * FSTAGE;
        const int j0 = jt * 64;
        const __nv_bfloat16* srcs[4] = {g_Kh, g_Kl, g_Vh, g_Vl};
        #pragma unroll
        for (int t = 0; t < 4; t++) {
            #pragma unroll
            for (int k = 0; k < 2; k++) {
                int c = tid + k * 256;
                int row = c >> 3, cx = c & 7;
                uint32_t dst = so + (uint32_t)t * FKV_TILE + row * FTROW + cx * 16;
                CPASYNC(dst, srcs[t] + kbase + (size_t)(j0 + row) * HD + cx * 8);
            }
        }
        CPCOMMIT();
    };

    issue_kv(0, 0);
    CPWAIT(0);
    __syncthreads();

    // Q fragments (register-resident for the whole block)
    const uint32_t aq = (lane & 7) + ((lane >> 3) & 1) * 8;
    const uint32_t ak = (lane >> 4) * 8;
    const uint32_t bq = (lane & 7) + (lane >> 4) * 8;
    const uint32_t bk = ((lane >> 3) & 1) * 8;

    uint32_t qhf[4][4], qlf[4][4];
    #pragma unroll
    for (int ks = 0; ks < 4; ks++) {
        uint32_t addr = sb + (wm * 16 + aq) * FTROW + (ks * 16 + ak) * 2;
        ldm4(qhf[ks], addr);
        ldm4(qlf[ks], addr + QSM_B);
    }

    float of[8][4];
    #pragma unroll
    for (int a = 0; a < 8; a++)
        #pragma unroll
        for (int e = 0; e < 4; e++) of[a][e] = 0.f;
    float m_i[2] = {-1e30f, -1e30f}, l_i[2] = {0.f, 0.f};

    for (int jt = 0; jt <= jmax; jt++) {
        if (jt + 1 <= jmax) { issue_kv((jt + 1) & 1, jt + 1); CPWAIT(1); }
        else                { CPWAIT(0); }
        __syncthreads();

        // fully-masked warps (first half at the odd diagonal tile) skip compute
        const bool skip = (q0 + wm * 16 + 15) < jt * 64;
        if (!skip) {
            const uint32_t so = sb + 2 * QSM_B + (uint32_t)(jt & 1) * FSTAGE;

            // ---- S = Q K^T (base-2 logits; Q pre-scaled) ----
            float sf[8][4];
            #pragma unroll
            for (int a = 0; a < 8; a++)
                #pragma unroll
                for (int e = 0; e < 4; e++) sf[a][e] = 0.f;

            #pragma unroll
            for (int ks = 0; ks < 4; ks++) {
                #pragma unroll
                for (int nb = 0; nb < 4; nb++) {
                    uint32_t addr = so + (nb * 16 + bq) * FTROW + (ks * 16 + bk) * 2;
                    uint32_t rh[4], rl[4];
                    ldm4(rh, addr);
                    ldm4(rl, addr + FKV_TILE);
                    mma16816(sf[2*nb],   qhf[ks], &rh[0]);
                    mma16816(sf[2*nb+1], qhf[ks], &rh[2]);
                    mma16816(sf[2*nb],   qhf[ks], &rl[0]);
                    mma16816(sf[2*nb+1], qhf[ks], &rl[2]);
                    mma16816(sf[2*nb],   qlf[ks], &rh[0]);
                    mma16816(sf[2*nb+1], qlf[ks], &rh[2]);
                }
            }

            // ---- online softmax (base 2) per row-half ----
            #pragma unroll
            for (int hh = 0; hh < 2; hh++) {
                const int grow = q0 + wm * 16 + hh * 8 + g;
                float mx = -1e30f;
                #pragma unroll
                for (int a = 0; a < 8; a++)
                    #pragma unroll
                    for (int e = 0; e < 2; e++) {
                        int col = jt * 64 + a * 8 + 2 * tg + e;
                        float v = sf[a][2*hh + e];
                        if (col > grow) v = -1e30f;
                        sf[a][2*hh + e] = v;
                        mx = fmaxf(mx, v);
                    }
                mx = fmaxf(mx, __shfl_xor_sync(0xffffffffu, mx, 1));
                mx = fmaxf(mx, __shfl_xor_sync(0xffffffffu, mx, 2));
                const float mnew  = fmaxf(m_i[hh], mx);
                const float alpha = exp2p(m_i[hh] - mnew);
                float rs = 0.f;
                #pragma unroll
                for (int a = 0; a < 8; a++)
                    #pragma unroll
                    for (int e = 0; e < 2; e++) {
                        float p = exp2p(sf[a][2*hh + e] - mnew);
                        sf[a][2*hh + e] = p;
                        rs += p;
                    }
                rs += __shfl_xor_sync(0xffffffffu, rs, 1);
                rs += __shfl_xor_sync(0xffffffffu, rs, 2);
                l_i[hh] = l_i[hh] * alpha + rs;
                m_i[hh] = mnew;
                #pragma unroll
                for (int a = 0; a < 8; a++)
                    #pragma unroll
                    for (int e = 0; e < 2; e++) of[a][2*hh + e] *= alpha;
            }

            // ---- O += P V (P repacked C->A in registers, hi/lo split) ----
            #pragma unroll
            for (int ks = 0; ks < 4; ks++) {
                uint32_t pah[4], pal[4];
                #pragma unroll
                for (int q = 0; q < 4; q++) {
                    float p0 = sf[2*ks + (q >> 1)][(q & 1) * 2 + 0];
                    float p1 = sf[2*ks + (q >> 1)][(q & 1) * 2 + 1];
                    __nv_bfloat16 h0 = __float2bfloat16(p0);
                    __nv_bfloat16 h1 = __float2bfloat16(p1);
                    __nv_bfloat162 hp; hp.x = h0; hp.y = h1;
                    pah[q] = *(uint32_t*)&hp;
                    pal[q] = packbf(p0 - __bfloat162float(h0), p1 - __bfloat162float(h1));
                }

                #pragma unroll
                for (int nb = 0; nb < 4; nb++) {
                    uint32_t addr = so + 2 * FKV_TILE + (ks * 16 + aq) * FTROW + (nb * 16 + ak) * 2;
                    uint32_t rh[4], rl[4];
                    ldm4t(rh, addr);
                    ldm4t(rl, addr + FKV_TILE);
                    mma16816(of[2*nb],   pah, &rh[0]);
                    mma16816(of[2*nb+1], pah, &rh[2]);
                    mma16816(of[2*nb],   pah, &rl[0]);
                    mma16816(of[2*nb+1], pah, &rl[2]);
                    mma16816(of[2*nb],   pal, &rh[0]);
                    mma16816(of[2*nb+1], pal, &rh[2]);
                }
            }
        }
        __syncthreads();
    }

    // ---- epilogue: normalize, split to bf16 hi/lo, write AO (standard layout) ----
    const size_t aobase = (size_t)b * LSEQ * DMODEL;
    #pragma unroll
    for (int hh = 0; hh < 2; hh++) {
        const float inv = 1.f / l_i[hh];
        const int row = q0 + wm * 16 + hh * 8 + g;
        #pragma unroll
        for (int a = 0; a < 8; a++) {
            float o0 = of[a][2*hh + 0] * inv;
            float o1 = of[a][2*hh + 1] * inv;
            __nv_bfloat16 h0 = __float2bfloat16(o0);
            __nv_bfloat16 h1 = __float2bfloat16(o1);
            __nv_bfloat162 hp; hp.x = h0; hp.y = h1;
            size_t off = aobase + (size_t)row * DMODEL + gh * HD + a * 8 + 2 * tg;
            *(uint32_t*)(g_aoh + off) = *(uint32_t*)&hp;
            *(uint32_t*)(g_aol + off) = packbf(o0 - __bfloat162float(h0), o1 - __bfloat162float(h1));
        }
    }
}

// ===================== Launch =====================
extern "C" void kernel_launch(void* const* d_in, const int* in_sizes, int n_in,
                              void* d_out, int out_size)
{
    const float* x    = (const float*)d_in[0];   // (2, 2048, 2048)
    const float* Wqkv = (const float*)d_in[2];   // (2048, 3072)
    const float* Wout = (const float*)d_in[3];   // (2048, 2048)
    float* out = (float*)d_out;                  // (2, 2048, 2048)

    (void)cudaFuncSetAttribute(gemm_mma<1>,
                               cudaFuncAttributeMaxDynamicSharedMemorySize, GSMEM);
    (void)cudaFuncSetAttribute(gemm_mma<0>,
                               cudaFuncAttributeMaxDynamicSharedMemorySize, GSMEM);
    (void)cudaFuncSetAttribute(fa_mma,
                               cudaFuncAttributeMaxDynamicSharedMemorySize, FA_SMEM);

    const int n4 = MROWS * DMODEL / 4;

    split_convert<<<(n4 + 255) / 256, 256>>>(x, n4);
    transpose_convert<<<dim3(NQKV / 32, DMODEL / 32), dim3(32, 8)>>>(Wqkv, NQKV, 0);
    transpose_convert<<<dim3(DMODEL / 32, DMODEL / 32), dim3(32, 8)>>>(Wout, DMODEL, 1);

    gemm_mma<1><<<dim3(NQKV / 256, MROWS / 128), GEMM_T, GSMEM>>>(nullptr);
    fa_mma<<<dim3(LSEQ / 128, 32, NB), FA_T, FA_SMEM>>>();
    gemm_mma<0><<<dim3(DMODEL / 256, MROWS / 128), GEMM_T, GSMEM>>>(out);
}